// round 1
// baseline (speedup 1.0000x reference)
#include <cuda_runtime.h>
#include <math.h>

// Problem constants
#define BB   16
#define SS   512
#define DD   512
#define HH   8
#define DK   64
#define DFFN 2048
#define MROWS (BB*SS)   // 8192

// ---------------- scratch (static device globals; no allocation) ----------------
__device__ float g_q  [MROWS*DD];
__device__ float g_k  [MROWS*DD];
__device__ float g_v  [MROWS*DD];
__device__ float g_ctx[MROWS*DD];
__device__ float g_ao [MROWS*DD];
__device__ float g_x1 [MROWS*DD];
__device__ float g_h1 [MROWS*DFFN];
__device__ float g_f2 [MROWS*DD];

// ---------------- SGEMM: C = A[MxK] @ B[KxN] + bias, optional ReLU ----------------
// 128x128 block tile, BK=8, 256 threads, 8x8 per-thread microtile.
template<bool RELU>
__global__ __launch_bounds__(256)
void sgemm_bias(const float* __restrict__ A, const float* __restrict__ B,
                const float* __restrict__ bias, float* __restrict__ C,
                int M, int N, int K)
{
    __shared__ float As[8][128];
    __shared__ float Bs[8][128];

    const int bm = blockIdx.y * 128;
    const int bn = blockIdx.x * 128;
    const int t  = threadIdx.x;

    const int aRow = t >> 1;            // 0..127
    const int aCol = (t & 1) * 4;       // 0 or 4
    const int bRow = t >> 5;            // 0..7
    const int bCol = (t & 31) * 4;      // 0..124

    const int ty = t >> 4;              // 0..15
    const int tx = t & 15;              // 0..15

    float acc[8][8];
#pragma unroll
    for (int m = 0; m < 8; m++)
#pragma unroll
        for (int n = 0; n < 8; n++) acc[m][n] = 0.f;

    const float* Aptr = A + (size_t)(bm + aRow) * K + aCol;
    const float* Bptr = B + (size_t)bRow * N + bn + bCol;

    for (int k0 = 0; k0 < K; k0 += 8) {
        float4 a4 = *(const float4*)Aptr;  Aptr += 8;
        float4 b4 = *(const float4*)Bptr;  Bptr += (size_t)8 * N;

        As[aCol + 0][aRow] = a4.x;
        As[aCol + 1][aRow] = a4.y;
        As[aCol + 2][aRow] = a4.z;
        As[aCol + 3][aRow] = a4.w;
        *(float4*)&Bs[bRow][bCol] = b4;
        __syncthreads();

#pragma unroll
        for (int kk = 0; kk < 8; kk++) {
            float ra[8], rb[8];
#pragma unroll
            for (int m = 0; m < 8; m++) ra[m] = As[kk][ty * 8 + m];
#pragma unroll
            for (int n = 0; n < 8; n++) rb[n] = Bs[kk][tx * 8 + n];
#pragma unroll
            for (int m = 0; m < 8; m++)
#pragma unroll
                for (int n = 0; n < 8; n++)
                    acc[m][n] = fmaf(ra[m], rb[n], acc[m][n]);
        }
        __syncthreads();
    }

    // epilogue
    float bv[8];
#pragma unroll
    for (int n = 0; n < 8; n++) bv[n] = bias[bn + tx * 8 + n];

#pragma unroll
    for (int m = 0; m < 8; m++) {
        float* Crow = C + (size_t)(bm + ty * 8 + m) * N + bn + tx * 8;
        float4 lo, hi;
        float v0 = acc[m][0] + bv[0], v1 = acc[m][1] + bv[1];
        float v2 = acc[m][2] + bv[2], v3 = acc[m][3] + bv[3];
        float v4 = acc[m][4] + bv[4], v5 = acc[m][5] + bv[5];
        float v6 = acc[m][6] + bv[6], v7 = acc[m][7] + bv[7];
        if (RELU) {
            v0 = fmaxf(v0, 0.f); v1 = fmaxf(v1, 0.f); v2 = fmaxf(v2, 0.f); v3 = fmaxf(v3, 0.f);
            v4 = fmaxf(v4, 0.f); v5 = fmaxf(v5, 0.f); v6 = fmaxf(v6, 0.f); v7 = fmaxf(v7, 0.f);
        }
        lo = make_float4(v0, v1, v2, v3);
        hi = make_float4(v4, v5, v6, v7);
        *(float4*)(Crow + 0) = lo;
        *(float4*)(Crow + 4) = hi;
    }
}

// ---------------- Fused AKT attention ----------------
// One block per (b, h, 16-query-row tile). 512 threads.
// SMEM layout (dynamic): sRaw[16*512] | sKV[64*65] | sQ[16*64]
#define TQ 16
#define SMEM_ATTN ((16*512 + 64*65 + 16*64) * (int)sizeof(float))

__global__ __launch_bounds__(512)
void attn_kernel(const float* __restrict__ Q, const float* __restrict__ K,
                 const float* __restrict__ V, const float* __restrict__ gammas,
                 float* __restrict__ O)
{
    extern __shared__ float smem[];
    float* sRaw = smem;                 // 16 x 512
    float* sKV  = smem + 16 * 512;      // 64 x 65 (padded)
    float* sQ   = sKV + 64 * 65;        // 16 x 64

    const int t  = threadIdx.x;
    const int qt = blockIdx.x;
    const int h  = blockIdx.y;
    const int b  = blockIdx.z;
    const int i0 = qt * TQ;

    // load Q tile
    for (int idx = t; idx < TQ * 64; idx += 512) {
        int r = idx >> 6, d = idx & 63;
        sQ[idx] = Q[((size_t)(b * SS + i0 + r)) * DD + h * 64 + d];
    }
    // init scores to "masked"
    for (int idx = t; idx < TQ * 512; idx += 512) sRaw[idx] = -1e32f;
    __syncthreads();

    const int nchunks = (i0 + TQ - 1) / 64 + 1;   // chunks with any j <= i_max

    // -------- Phase A: raw scores --------
    for (int c = 0; c < nchunks; c++) {
        const int j0 = c * 64;
        for (int idx = t; idx < 64 * 64; idx += 512) {
            int j = idx >> 6, d = idx & 63;
            sKV[j * 65 + d] = K[((size_t)(b * SS + j0 + j)) * DD + h * 64 + d];
        }
        __syncthreads();
#pragma unroll
        for (int half = 0; half < 2; half++) {
            int p  = t + half * 512;
            int r  = p >> 6;             // 0..15
            int j  = p & 63;
            int ig = i0 + r, jg = j0 + j;
            float a = 0.f;
            const float* q = sQ + r * 64;
            const float* k = sKV + j * 65;
#pragma unroll
            for (int d = 0; d < 64; d++) a = fmaf(q[d], k[d], a);
            if (jg <= ig) sRaw[r * 512 + jg] = a * 0.125f;  // 1/sqrt(64)
        }
        __syncthreads();
    }

    // -------- Phase B: softmax -> cumsum -> distance effect -> softmax (warp per row) --------
    {
        const int w = t >> 5, lane = t & 31;
        const int ig = i0 + w;
        float g  = gammas[h];
        float sp = (g > 20.f) ? g : log1pf(expf(g));
        float gamma = -sp;

        float* row = sRaw + w * 512;
        float vals[16];
#pragma unroll
        for (int m = 0; m < 16; m++) vals[m] = row[lane * 16 + m];

        // first softmax
        float mx = -1e32f;
#pragma unroll
        for (int m = 0; m < 16; m++) mx = fmaxf(mx, vals[m]);
#pragma unroll
        for (int off = 16; off > 0; off >>= 1) mx = fmaxf(mx, __shfl_xor_sync(0xffffffffu, mx, off));

        float p[16]; float s = 0.f;
#pragma unroll
        for (int m = 0; m < 16; m++) { p[m] = expf(vals[m] - mx); s += p[m]; }
#pragma unroll
        for (int off = 16; off > 0; off >>= 1) s += __shfl_xor_sync(0xffffffffu, s, off);
        const float inv = 1.f / s;

        // inclusive cumsum of normalized probs
        float local = 0.f; float cum[16];
#pragma unroll
        for (int m = 0; m < 16; m++) { local += p[m] * inv; cum[m] = local; }
        float run = local;
#pragma unroll
        for (int off = 1; off < 32; off <<= 1) {
            float vv = __shfl_up_sync(0xffffffffu, run, off);
            if (lane >= off) run += vv;
        }
        const float prefix = run - local;
        const float total  = __shfl_sync(0xffffffffu, run, 31);

        // distance effect, modulate raw
#pragma unroll
        for (int m = 0; m < 16; m++) {
            int jg = lane * 16 + m;
            float suffix = fmaxf(total - (prefix + cum[m]), 0.f);
            float pe = fabsf((float)(ig - jg));
            float dist = sqrtf(suffix * pe);
            float eff = expf(dist * gamma);
            eff = fminf(fmaxf(eff, 1e-5f), 1e5f);
            vals[m] = vals[m] * eff;     // masked entries stay ~-1e32*eff -> effectively -inf
        }

        // second softmax
        float mx2 = -1e32f;
#pragma unroll
        for (int m = 0; m < 16; m++) mx2 = fmaxf(mx2, vals[m]);
#pragma unroll
        for (int off = 16; off > 0; off >>= 1) mx2 = fmaxf(mx2, __shfl_xor_sync(0xffffffffu, mx2, off));
        float s2 = 0.f;
#pragma unroll
        for (int m = 0; m < 16; m++) { vals[m] = expf(vals[m] - mx2); s2 += vals[m]; }
#pragma unroll
        for (int off = 16; off > 0; off >>= 1) s2 += __shfl_xor_sync(0xffffffffu, s2, off);
        const float inv2 = 1.f / s2;
#pragma unroll
        for (int m = 0; m < 16; m++) row[lane * 16 + m] = vals[m] * inv2;
    }
    __syncthreads();

    // -------- Phase C: out = P2 @ V --------
    const int d  = t & 63;
    const int ra = t >> 6;               // 0..7  (rows ra and ra+8)
    float acca = 0.f, accb = 0.f;
    for (int c = 0; c < nchunks; c++) {
        const int j0 = c * 64;
        for (int idx = t; idx < 64 * 64; idx += 512) {
            int j = idx >> 6, dd = idx & 63;
            sKV[j * 65 + dd] = V[((size_t)(b * SS + j0 + j)) * DD + h * 64 + dd];
        }
        __syncthreads();
#pragma unroll
        for (int j = 0; j < 64; j++) {
            float vjd = sKV[j * 65 + d];
            acca = fmaf(sRaw[ra       * 512 + j0 + j], vjd, acca);
            accb = fmaf(sRaw[(ra + 8) * 512 + j0 + j], vjd, accb);
        }
        __syncthreads();
    }
    O[((size_t)(b * SS + i0 + ra    )) * DD + h * 64 + d] = acca;
    O[((size_t)(b * SS + i0 + ra + 8)) * DD + h * 64 + d] = accb;
}

// ---------------- residual add + LayerNorm (one block per row of 512) ----------------
__global__ __launch_bounds__(256)
void add_ln(const float* __restrict__ A, const float* __restrict__ B,
            const float* __restrict__ g, const float* __restrict__ be,
            float* __restrict__ O)
{
    const int row = blockIdx.x;
    const int t = threadIdx.x;
    const float* a = A + (size_t)row * DD;
    const float* b = B + (size_t)row * DD;

    float x0 = a[t] + b[t];
    float x1 = a[t + 256] + b[t + 256];
    float s  = x0 + x1;
    float sq = x0 * x0 + x1 * x1;

    __shared__ float rs[8], rq[8];
    __shared__ float sMu, sRstd;
    const int lane = t & 31, w = t >> 5;
#pragma unroll
    for (int off = 16; off > 0; off >>= 1) {
        s  += __shfl_xor_sync(0xffffffffu, s, off);
        sq += __shfl_xor_sync(0xffffffffu, sq, off);
    }
    if (lane == 0) { rs[w] = s; rq[w] = sq; }
    __syncthreads();
    if (t == 0) {
        float S = 0.f, SQ = 0.f;
#pragma unroll
        for (int i = 0; i < 8; i++) { S += rs[i]; SQ += rq[i]; }
        float mu = S * (1.f / 512.f);
        float var = fmaxf(SQ * (1.f / 512.f) - mu * mu, 0.f);
        sMu = mu;
        sRstd = rsqrtf(var + 1e-5f);
    }
    __syncthreads();
    const float mu = sMu, rstd = sRstd;
    O[(size_t)row * DD + t]       = (x0 - mu) * rstd * g[t]       + be[t];
    O[(size_t)row * DD + t + 256] = (x1 - mu) * rstd * g[t + 256] + be[t + 256];
}

// ---------------- launch ----------------
extern "C" void kernel_launch(void* const* d_in, const int* in_sizes, int n_in,
                              void* d_out, int out_size)
{
    const float* query  = (const float*)d_in[0];
    const float* key    = (const float*)d_in[1];
    const float* values = (const float*)d_in[2];
    const float* Wk     = (const float*)d_in[3];
    const float* bk     = (const float*)d_in[4];
    const float* Wv     = (const float*)d_in[5];
    const float* bv     = (const float*)d_in[6];
    const float* Wo     = (const float*)d_in[7];
    const float* bo     = (const float*)d_in[8];
    const float* gammas = (const float*)d_in[9];
    const float* ln1_g  = (const float*)d_in[10];
    const float* ln1_b  = (const float*)d_in[11];
    const float* W1     = (const float*)d_in[12];
    const float* b1     = (const float*)d_in[13];
    const float* W2     = (const float*)d_in[14];
    const float* b2     = (const float*)d_in[15];
    const float* ln2_g  = (const float*)d_in[16];
    const float* ln2_b  = (const float*)d_in[17];
    // d_in[18] = mask (always 1 in this dataset): causal j<=i, no zero_pad.
    float* out = (float*)d_out;

    float *q, *k, *v, *ctx, *ao, *x1, *h1, *f2;
    cudaGetSymbolAddress((void**)&q,   g_q);
    cudaGetSymbolAddress((void**)&k,   g_k);
    cudaGetSymbolAddress((void**)&v,   g_v);
    cudaGetSymbolAddress((void**)&ctx, g_ctx);
    cudaGetSymbolAddress((void**)&ao,  g_ao);
    cudaGetSymbolAddress((void**)&x1,  g_x1);
    cudaGetSymbolAddress((void**)&h1,  g_h1);
    cudaGetSymbolAddress((void**)&f2,  g_f2);

    cudaFuncSetAttribute(attn_kernel, cudaFuncAttributeMaxDynamicSharedMemorySize, SMEM_ATTN);

    const dim3 gProj(DD / 128, MROWS / 128);     // (4, 64)
    const dim3 gFF1 (DFFN / 128, MROWS / 128);   // (16, 64)

    // projections (kq_same=True: q and k both use Wk)
    sgemm_bias<false><<<gProj, 256>>>(query,  Wk, bk, q, MROWS, DD, DD);
    sgemm_bias<false><<<gProj, 256>>>(key,    Wk, bk, k, MROWS, DD, DD);
    sgemm_bias<false><<<gProj, 256>>>(values, Wv, bv, v, MROWS, DD, DD);

    // fused attention (scores -> softmax -> cumsum -> effect -> softmax -> PV)
    attn_kernel<<<dim3(SS / TQ, HH, BB), 512, SMEM_ATTN>>>(q, k, v, gammas, ctx);

    // output projection
    sgemm_bias<false><<<gProj, 256>>>(ctx, Wo, bo, ao, MROWS, DD, DD);

    // residual + LN1
    add_ln<<<MROWS, 256>>>(query, ao, ln1_g, ln1_b, x1);

    // FFN
    sgemm_bias<true ><<<gFF1, 256>>>(x1, W1, b1, h1, MROWS, DFFN, DD);
    sgemm_bias<false><<<gProj, 256>>>(h1, W2, b2, f2, MROWS, DD, DFFN);

    // residual + LN2 -> output
    add_ln<<<MROWS, 256>>>(x1, f2, ln2_g, ln2_b, out);
}

// round 4
// speedup vs baseline: 1.9127x; 1.9127x over previous
#include <cuda_runtime.h>
#include <cstdint>
#include <math.h>

// Problem constants
#define BB   16
#define SS   512
#define DD   512
#define HH   8
#define DK   64
#define DFFN 2048
#define MROWS (BB*SS)   // 8192

// ---------------- scratch (static device globals; no allocation) ----------------
__device__ float g_q  [MROWS*DD];
__device__ float g_k  [MROWS*DD];
__device__ float g_v  [MROWS*DD];
__device__ float g_ctx[MROWS*DD];
__device__ float g_ao [MROWS*DD];
__device__ float g_x1 [MROWS*DD];
__device__ float g_h1 [MROWS*DFFN];
__device__ float g_f2 [MROWS*DD];

// ---------------- helpers ----------------
__device__ __forceinline__ uint32_t smem_to_u32(const void* p) {
    uint32_t a;
    asm("{ .reg .u64 tmp; cvta.to.shared.u64 tmp, %1; cvt.u32.u64 %0, tmp; }" : "=r"(a) : "l"(p));
    return a;
}
#define CP_ASYNC16(saddr, gptr) \
    asm volatile("cp.async.cg.shared.global [%0], [%1], 16;" :: "r"(saddr), "l"(gptr))
#define CP_COMMIT() asm volatile("cp.async.commit_group;" ::: "memory")
#define CP_WAIT0()  asm volatile("cp.async.wait_group 0;" ::: "memory")

// mma.sync m16n8k8 tf32 (A row-major, B col-major, fp32 accum)
__device__ __forceinline__ void mma_tf32(float* c, const uint32_t* a, const uint32_t* b) {
    asm volatile(
        "mma.sync.aligned.m16n8k8.row.col.f32.tf32.tf32.f32 "
        "{%0,%1,%2,%3}, {%4,%5,%6,%7}, {%8,%9}, {%0,%1,%2,%3};"
        : "+f"(c[0]), "+f"(c[1]), "+f"(c[2]), "+f"(c[3])
        : "r"(a[0]), "r"(a[1]), "r"(a[2]), "r"(a[3]), "r"(b[0]), "r"(b[1]));
}

// ========================= tf32 mma.sync GEMM =========================
// C[M,N] = A[M,K] @ W[K,N] + bias (optional ReLU).
// 128x128 tile, BK=32, 256 threads = 8 warps (2m x 4n), each warp 64x32.
// SMEM: A tile [128][36] (m-major, pitch 36 floats), W tile [32][132] (k-major, pitch 132).
#define AP 36
#define BP 132
#define A_TILE (128*AP)                 // floats
#define B_TILE (32*BP)                  // floats
#define GEMM_BUF (A_TILE + B_TILE)      // floats per stage
#define GEMM_SMEM (2*GEMM_BUF*(int)sizeof(float))

__device__ __forceinline__ void fill_tiles(const float* __restrict__ A,
                                           const float* __restrict__ W,
                                           int K, int N, int bm, int bn, int kc,
                                           uint32_t sA, uint32_t sB, int t)
{
    // A: 128 rows x 32 k (1024 float4, k-contiguous)
#pragma unroll
    for (int i = 0; i < 4; i++) {
        int id  = t + i * 256;
        int row = id >> 3, k4 = id & 7;
        const float* src = A + (size_t)(bm + row) * K + kc * 32 + k4 * 4;
        CP_ASYNC16(sA + (uint32_t)(row * AP + k4 * 4) * 4u, src);
    }
    // W: 32 k-rows x 128 n (1024 float4, n-contiguous)
#pragma unroll
    for (int i = 0; i < 4; i++) {
        int id   = t + i * 256;
        int krow = id >> 5, n4 = id & 31;
        const float* src = W + (size_t)(kc * 32 + krow) * N + bn + n4 * 4;
        CP_ASYNC16(sB + (uint32_t)(krow * BP + n4 * 4) * 4u, src);
    }
}

template<bool RELU>
__global__ __launch_bounds__(256)
void gemm_mma(const float* __restrict__ A, const float* __restrict__ W,
              const float* __restrict__ bias, float* __restrict__ C,
              int M, int N, int K)
{
    extern __shared__ __align__(16) float smem_g[];
    const int t    = threadIdx.x;
    const int bm   = blockIdx.y * 128;
    const int bn   = blockIdx.x * 128;
    const int lane = t & 31, wid = t >> 5;
    const int g    = lane >> 2, tg = lane & 3;
    const int wm   = (wid >> 2) * 64;     // warp m offset: 0 or 64
    const int wn   = (wid & 3) * 32;      // warp n offset: 0,32,64,96
    const uint32_t sbase = smem_to_u32(smem_g);

    float acc[4][4][4];
#pragma unroll
    for (int mt = 0; mt < 4; mt++)
#pragma unroll
        for (int nt = 0; nt < 4; nt++)
#pragma unroll
            for (int r = 0; r < 4; r++) acc[mt][nt][r] = 0.f;

    const int nk = K >> 5;

    fill_tiles(A, W, K, N, bm, bn, 0, sbase, sbase + A_TILE * 4, t);
    CP_COMMIT();

    for (int kc = 0; kc < nk; kc++) {
        CP_WAIT0();
        __syncthreads();
        if (kc + 1 < nk) {
            const uint32_t off = ((kc + 1) & 1) * (uint32_t)(GEMM_BUF * 4);
            fill_tiles(A, W, K, N, bm, bn, kc + 1, sbase + off, sbase + off + A_TILE * 4, t);
            CP_COMMIT();
        }
        const float* aS = smem_g + (kc & 1) * GEMM_BUF;
        const float* bS = aS + A_TILE;

#pragma unroll
        for (int ks = 0; ks < 4; ks++) {
            const int k0 = ks * 8;
            uint32_t af[4][4];
#pragma unroll
            for (int mt = 0; mt < 4; mt++) {
                const int mrow = wm + mt * 16 + g;
                af[mt][0] = __float_as_uint(aS[(mrow    ) * AP + k0 + tg    ]);
                af[mt][1] = __float_as_uint(aS[(mrow + 8) * AP + k0 + tg    ]);
                af[mt][2] = __float_as_uint(aS[(mrow    ) * AP + k0 + tg + 4]);
                af[mt][3] = __float_as_uint(aS[(mrow + 8) * AP + k0 + tg + 4]);
            }
            uint32_t bf[4][2];
#pragma unroll
            for (int nt = 0; nt < 4; nt++) {
                const int ncol = wn + nt * 8 + g;
                bf[nt][0] = __float_as_uint(bS[(k0 + tg    ) * BP + ncol]);
                bf[nt][1] = __float_as_uint(bS[(k0 + tg + 4) * BP + ncol]);
            }
#pragma unroll
            for (int mt = 0; mt < 4; mt++)
#pragma unroll
                for (int nt = 0; nt < 4; nt++)
                    mma_tf32(acc[mt][nt], af[mt], bf[nt]);
        }
    }

    // epilogue: c0,c1 = (row g, cols 2tg,2tg+1); c2,c3 = row g+8
#pragma unroll
    for (int mt = 0; mt < 4; mt++) {
#pragma unroll
        for (int nt = 0; nt < 4; nt++) {
            const int row0 = bm + wm + mt * 16 + g;
            const int col  = bn + wn + nt * 8 + 2 * tg;
            float b0 = bias[col], b1 = bias[col + 1];
            float v0 = acc[mt][nt][0] + b0, v1 = acc[mt][nt][1] + b1;
            float v2 = acc[mt][nt][2] + b0, v3 = acc[mt][nt][3] + b1;
            if (RELU) {
                v0 = fmaxf(v0, 0.f); v1 = fmaxf(v1, 0.f);
                v2 = fmaxf(v2, 0.f); v3 = fmaxf(v3, 0.f);
            }
            *(float2*)(C + (size_t)row0 * N + col)       = make_float2(v0, v1);
            *(float2*)(C + (size_t)(row0 + 8) * N + col) = make_float2(v2, v3);
        }
    }
}

// ---------------- Fused AKT attention (unchanged from R1) ----------------
#define TQ 16
#define SMEM_ATTN ((16*512 + 64*65 + 16*64) * (int)sizeof(float))

__global__ __launch_bounds__(512)
void attn_kernel(const float* __restrict__ Q, const float* __restrict__ K,
                 const float* __restrict__ V, const float* __restrict__ gammas,
                 float* __restrict__ O)
{
    extern __shared__ float smem[];
    float* sRaw = smem;
    float* sKV  = smem + 16 * 512;
    float* sQ   = sKV + 64 * 65;

    const int t  = threadIdx.x;
    const int qt = blockIdx.x;
    const int h  = blockIdx.y;
    const int b  = blockIdx.z;
    const int i0 = qt * TQ;

    for (int idx = t; idx < TQ * 64; idx += 512) {
        int r = idx >> 6, d = idx & 63;
        sQ[idx] = Q[((size_t)(b * SS + i0 + r)) * DD + h * 64 + d];
    }
    for (int idx = t; idx < TQ * 512; idx += 512) sRaw[idx] = -1e32f;
    __syncthreads();

    const int nchunks = (i0 + TQ - 1) / 64 + 1;

    for (int c = 0; c < nchunks; c++) {
        const int j0 = c * 64;
        for (int idx = t; idx < 64 * 64; idx += 512) {
            int j = idx >> 6, d = idx & 63;
            sKV[j * 65 + d] = K[((size_t)(b * SS + j0 + j)) * DD + h * 64 + d];
        }
        __syncthreads();
#pragma unroll
        for (int half = 0; half < 2; half++) {
            int p  = t + half * 512;
            int r  = p >> 6;
            int j  = p & 63;
            int ig = i0 + r, jg = j0 + j;
            float a = 0.f;
            const float* q = sQ + r * 64;
            const float* k = sKV + j * 65;
#pragma unroll
            for (int d = 0; d < 64; d++) a = fmaf(q[d], k[d], a);
            if (jg <= ig) sRaw[r * 512 + jg] = a * 0.125f;
        }
        __syncthreads();
    }

    {
        const int w = t >> 5, lane = t & 31;
        const int ig = i0 + w;
        float g  = gammas[h];
        float sp = (g > 20.f) ? g : log1pf(expf(g));
        float gamma = -sp;

        float* row = sRaw + w * 512;
        float vals[16];
#pragma unroll
        for (int m = 0; m < 16; m++) vals[m] = row[lane * 16 + m];

        float mx = -1e32f;
#pragma unroll
        for (int m = 0; m < 16; m++) mx = fmaxf(mx, vals[m]);
#pragma unroll
        for (int off = 16; off > 0; off >>= 1) mx = fmaxf(mx, __shfl_xor_sync(0xffffffffu, mx, off));

        float p[16]; float s = 0.f;
#pragma unroll
        for (int m = 0; m < 16; m++) { p[m] = expf(vals[m] - mx); s += p[m]; }
#pragma unroll
        for (int off = 16; off > 0; off >>= 1) s += __shfl_xor_sync(0xffffffffu, s, off);
        const float inv = 1.f / s;

        float local = 0.f; float cum[16];
#pragma unroll
        for (int m = 0; m < 16; m++) { local += p[m] * inv; cum[m] = local; }
        float run = local;
#pragma unroll
        for (int off = 1; off < 32; off <<= 1) {
            float vv = __shfl_up_sync(0xffffffffu, run, off);
            if (lane >= off) run += vv;
        }
        const float prefix = run - local;
        const float total  = __shfl_sync(0xffffffffu, run, 31);

#pragma unroll
        for (int m = 0; m < 16; m++) {
            int jg = lane * 16 + m;
            float suffix = fmaxf(total - (prefix + cum[m]), 0.f);
            float pe = fabsf((float)(ig - jg));
            float dist = sqrtf(suffix * pe);
            float eff = expf(dist * gamma);
            eff = fminf(fmaxf(eff, 1e-5f), 1e5f);
            vals[m] = vals[m] * eff;
        }

        float mx2 = -1e32f;
#pragma unroll
        for (int m = 0; m < 16; m++) mx2 = fmaxf(mx2, vals[m]);
#pragma unroll
        for (int off = 16; off > 0; off >>= 1) mx2 = fmaxf(mx2, __shfl_xor_sync(0xffffffffu, mx2, off));
        float s2 = 0.f;
#pragma unroll
        for (int m = 0; m < 16; m++) { vals[m] = expf(vals[m] - mx2); s2 += vals[m]; }
#pragma unroll
        for (int off = 16; off > 0; off >>= 1) s2 += __shfl_xor_sync(0xffffffffu, s2, off);
        const float inv2 = 1.f / s2;
#pragma unroll
        for (int m = 0; m < 16; m++) row[lane * 16 + m] = vals[m] * inv2;
    }
    __syncthreads();

    const int d  = t & 63;
    const int ra = t >> 6;
    float acca = 0.f, accb = 0.f;
    for (int c = 0; c < nchunks; c++) {
        const int j0 = c * 64;
        for (int idx = t; idx < 64 * 64; idx += 512) {
            int j = idx >> 6, dd = idx & 63;
            sKV[j * 65 + dd] = V[((size_t)(b * SS + j0 + j)) * DD + h * 64 + dd];
        }
        __syncthreads();
#pragma unroll
        for (int j = 0; j < 64; j++) {
            float vjd = sKV[j * 65 + d];
            acca = fmaf(sRaw[ra       * 512 + j0 + j], vjd, acca);
            accb = fmaf(sRaw[(ra + 8) * 512 + j0 + j], vjd, accb);
        }
        __syncthreads();
    }
    O[((size_t)(b * SS + i0 + ra    )) * DD + h * 64 + d] = acca;
    O[((size_t)(b * SS + i0 + ra + 8)) * DD + h * 64 + d] = accb;
}

// ---------------- residual add + LayerNorm ----------------
__global__ __launch_bounds__(256)
void add_ln(const float* __restrict__ A, const float* __restrict__ B,
            const float* __restrict__ g, const float* __restrict__ be,
            float* __restrict__ O)
{
    const int row = blockIdx.x;
    const int t = threadIdx.x;
    const float* a = A + (size_t)row * DD;
    const float* b = B + (size_t)row * DD;

    float x0 = a[t] + b[t];
    float x1 = a[t + 256] + b[t + 256];
    float s  = x0 + x1;
    float sq = x0 * x0 + x1 * x1;

    __shared__ float rs[8], rq[8];
    __shared__ float sMu, sRstd;
    const int lane = t & 31, w = t >> 5;
#pragma unroll
    for (int off = 16; off > 0; off >>= 1) {
        s  += __shfl_xor_sync(0xffffffffu, s, off);
        sq += __shfl_xor_sync(0xffffffffu, sq, off);
    }
    if (lane == 0) { rs[w] = s; rq[w] = sq; }
    __syncthreads();
    if (t == 0) {
        float S = 0.f, SQ = 0.f;
#pragma unroll
        for (int i = 0; i < 8; i++) { S += rs[i]; SQ += rq[i]; }
        float mu = S * (1.f / 512.f);
        float var = fmaxf(SQ * (1.f / 512.f) - mu * mu, 0.f);
        sMu = mu;
        sRstd = rsqrtf(var + 1e-5f);
    }
    __syncthreads();
    const float mu = sMu, rstd = sRstd;
    O[(size_t)row * DD + t]       = (x0 - mu) * rstd * g[t]       + be[t];
    O[(size_t)row * DD + t + 256] = (x1 - mu) * rstd * g[t + 256] + be[t + 256];
}

// ---------------- launch ----------------
extern "C" void kernel_launch(void* const* d_in, const int* in_sizes, int n_in,
                              void* d_out, int out_size)
{
    const float* query  = (const float*)d_in[0];
    const float* key    = (const float*)d_in[1];
    const float* values = (const float*)d_in[2];
    const float* Wk     = (const float*)d_in[3];
    const float* bk     = (const float*)d_in[4];
    const float* Wv     = (const float*)d_in[5];
    const float* bv     = (const float*)d_in[6];
    const float* Wo     = (const float*)d_in[7];
    const float* bo     = (const float*)d_in[8];
    const float* gammas = (const float*)d_in[9];
    const float* ln1_g  = (const float*)d_in[10];
    const float* ln1_b  = (const float*)d_in[11];
    const float* W1     = (const float*)d_in[12];
    const float* b1     = (const float*)d_in[13];
    const float* W2     = (const float*)d_in[14];
    const float* b2     = (const float*)d_in[15];
    const float* ln2_g  = (const float*)d_in[16];
    const float* ln2_b  = (const float*)d_in[17];
    float* out = (float*)d_out;

    float *q, *k, *v, *ctx, *ao, *x1, *h1, *f2;
    cudaGetSymbolAddress((void**)&q,   g_q);
    cudaGetSymbolAddress((void**)&k,   g_k);
    cudaGetSymbolAddress((void**)&v,   g_v);
    cudaGetSymbolAddress((void**)&ctx, g_ctx);
    cudaGetSymbolAddress((void**)&ao,  g_ao);
    cudaGetSymbolAddress((void**)&x1,  g_x1);
    cudaGetSymbolAddress((void**)&h1,  g_h1);
    cudaGetSymbolAddress((void**)&f2,  g_f2);

    cudaFuncSetAttribute(attn_kernel, cudaFuncAttributeMaxDynamicSharedMemorySize, SMEM_ATTN);
    cudaFuncSetAttribute(gemm_mma<false>, cudaFuncAttributeMaxDynamicSharedMemorySize, GEMM_SMEM);
    cudaFuncSetAttribute(gemm_mma<true>,  cudaFuncAttributeMaxDynamicSharedMemorySize, GEMM_SMEM);

    const dim3 gProj(DD / 128,   MROWS / 128);   // (4, 64)
    const dim3 gFF1 (DFFN / 128, MROWS / 128);   // (16, 64)

    // projections (kq_same=True: q and k both use Wk)
    gemm_mma<false><<<gProj, 256, GEMM_SMEM>>>(query,  Wk, bk, q, MROWS, DD, DD);
    gemm_mma<false><<<gProj, 256, GEMM_SMEM>>>(key,    Wk, bk, k, MROWS, DD, DD);
    gemm_mma<false><<<gProj, 256, GEMM_SMEM>>>(values, Wv, bv, v, MROWS, DD, DD);

    attn_kernel<<<dim3(SS / TQ, HH, BB), 512, SMEM_ATTN>>>(q, k, v, gammas, ctx);

    gemm_mma<false><<<gProj, 256, GEMM_SMEM>>>(ctx, Wo, bo, ao, MROWS, DD, DD);

    add_ln<<<MROWS, 256>>>(query, ao, ln1_g, ln1_b, x1);

    gemm_mma<true ><<<gFF1, 256, GEMM_SMEM>>>(x1, W1, b1, h1, MROWS, DFFN, DD);
    gemm_mma<false><<<gProj, 256, GEMM_SMEM>>>(h1, W2, b2, f2, MROWS, DD, DFFN);

    add_ln<<<MROWS, 256>>>(x1, f2, ln2_g, ln2_b, out);
}

// round 5
// speedup vs baseline: 3.3025x; 1.7266x over previous
#include <cuda_runtime.h>
#include <cstdint>
#include <math.h>

// Problem constants
#define BB   16
#define SS   512
#define DD   512
#define HH   8
#define DK   64
#define DFFN 2048
#define MROWS (BB*SS)   // 8192

// ---------------- scratch (static device globals; no allocation) ----------------
__device__ float g_q  [MROWS*DD];
__device__ float g_k  [MROWS*DD];
__device__ float g_v  [MROWS*DD];
__device__ float g_ctx[MROWS*DD];
__device__ float g_ao [MROWS*DD];
__device__ float g_x1 [MROWS*DD];
__device__ float g_h1 [MROWS*DFFN];
__device__ float g_f2 [MROWS*DD];

// ---------------- helpers ----------------
__device__ __forceinline__ uint32_t smem_to_u32(const void* p) {
    uint32_t a;
    asm("{ .reg .u64 tmp; cvta.to.shared.u64 tmp, %1; cvt.u32.u64 %0, tmp; }" : "=r"(a) : "l"(p));
    return a;
}
#define CP_ASYNC16(saddr, gptr) \
    asm volatile("cp.async.cg.shared.global [%0], [%1], 16;" :: "r"(saddr), "l"(gptr))
#define CP_COMMIT() asm volatile("cp.async.commit_group;" ::: "memory")
#define CP_WAIT0()  asm volatile("cp.async.wait_group 0;" ::: "memory")

// mma.sync m16n8k8 tf32 (A row-major, B col-major, fp32 accum)
__device__ __forceinline__ void mma_tf32(float* c, const uint32_t* a, const uint32_t* b) {
    asm volatile(
        "mma.sync.aligned.m16n8k8.row.col.f32.tf32.tf32.f32 "
        "{%0,%1,%2,%3}, {%4,%5,%6,%7}, {%8,%9}, {%0,%1,%2,%3};"
        : "+f"(c[0]), "+f"(c[1]), "+f"(c[2]), "+f"(c[3])
        : "r"(a[0]), "r"(a[1]), "r"(a[2]), "r"(a[3]), "r"(b[0]), "r"(b[1]));
}

// ========================= tf32 mma.sync GEMM (unchanged from R4) =========================
#define AP 36
#define BP 132
#define A_TILE (128*AP)
#define B_TILE (32*BP)
#define GEMM_BUF (A_TILE + B_TILE)
#define GEMM_SMEM (2*GEMM_BUF*(int)sizeof(float))

__device__ __forceinline__ void fill_tiles(const float* __restrict__ A,
                                           const float* __restrict__ W,
                                           int K, int N, int bm, int bn, int kc,
                                           uint32_t sA, uint32_t sB, int t)
{
#pragma unroll
    for (int i = 0; i < 4; i++) {
        int id  = t + i * 256;
        int row = id >> 3, k4 = id & 7;
        const float* src = A + (size_t)(bm + row) * K + kc * 32 + k4 * 4;
        CP_ASYNC16(sA + (uint32_t)(row * AP + k4 * 4) * 4u, src);
    }
#pragma unroll
    for (int i = 0; i < 4; i++) {
        int id   = t + i * 256;
        int krow = id >> 5, n4 = id & 31;
        const float* src = W + (size_t)(kc * 32 + krow) * N + bn + n4 * 4;
        CP_ASYNC16(sB + (uint32_t)(krow * BP + n4 * 4) * 4u, src);
    }
}

template<bool RELU>
__global__ __launch_bounds__(256)
void gemm_mma(const float* __restrict__ A, const float* __restrict__ W,
              const float* __restrict__ bias, float* __restrict__ C,
              int M, int N, int K)
{
    extern __shared__ __align__(16) float smem_g[];
    const int t    = threadIdx.x;
    const int bm   = blockIdx.y * 128;
    const int bn   = blockIdx.x * 128;
    const int lane = t & 31, wid = t >> 5;
    const int g    = lane >> 2, tg = lane & 3;
    const int wm   = (wid >> 2) * 64;
    const int wn   = (wid & 3) * 32;
    const uint32_t sbase = smem_to_u32(smem_g);

    float acc[4][4][4];
#pragma unroll
    for (int mt = 0; mt < 4; mt++)
#pragma unroll
        for (int nt = 0; nt < 4; nt++)
#pragma unroll
            for (int r = 0; r < 4; r++) acc[mt][nt][r] = 0.f;

    const int nk = K >> 5;

    fill_tiles(A, W, K, N, bm, bn, 0, sbase, sbase + A_TILE * 4, t);
    CP_COMMIT();

    for (int kc = 0; kc < nk; kc++) {
        CP_WAIT0();
        __syncthreads();
        if (kc + 1 < nk) {
            const uint32_t off = ((kc + 1) & 1) * (uint32_t)(GEMM_BUF * 4);
            fill_tiles(A, W, K, N, bm, bn, kc + 1, sbase + off, sbase + off + A_TILE * 4, t);
            CP_COMMIT();
        }
        const float* aS = smem_g + (kc & 1) * GEMM_BUF;
        const float* bS = aS + A_TILE;

#pragma unroll
        for (int ks = 0; ks < 4; ks++) {
            const int k0 = ks * 8;
            uint32_t af[4][4];
#pragma unroll
            for (int mt = 0; mt < 4; mt++) {
                const int mrow = wm + mt * 16 + g;
                af[mt][0] = __float_as_uint(aS[(mrow    ) * AP + k0 + tg    ]);
                af[mt][1] = __float_as_uint(aS[(mrow + 8) * AP + k0 + tg    ]);
                af[mt][2] = __float_as_uint(aS[(mrow    ) * AP + k0 + tg + 4]);
                af[mt][3] = __float_as_uint(aS[(mrow + 8) * AP + k0 + tg + 4]);
            }
            uint32_t bf[4][2];
#pragma unroll
            for (int nt = 0; nt < 4; nt++) {
                const int ncol = wn + nt * 8 + g;
                bf[nt][0] = __float_as_uint(bS[(k0 + tg    ) * BP + ncol]);
                bf[nt][1] = __float_as_uint(bS[(k0 + tg + 4) * BP + ncol]);
            }
#pragma unroll
            for (int mt = 0; mt < 4; mt++)
#pragma unroll
                for (int nt = 0; nt < 4; nt++)
                    mma_tf32(acc[mt][nt], af[mt], bf[nt]);
        }
    }

#pragma unroll
    for (int mt = 0; mt < 4; mt++) {
#pragma unroll
        for (int nt = 0; nt < 4; nt++) {
            const int row0 = bm + wm + mt * 16 + g;
            const int col  = bn + wn + nt * 8 + 2 * tg;
            float b0 = bias[col], b1 = bias[col + 1];
            float v0 = acc[mt][nt][0] + b0, v1 = acc[mt][nt][1] + b1;
            float v2 = acc[mt][nt][2] + b0, v3 = acc[mt][nt][3] + b1;
            if (RELU) {
                v0 = fmaxf(v0, 0.f); v1 = fmaxf(v1, 0.f);
                v2 = fmaxf(v2, 0.f); v3 = fmaxf(v3, 0.f);
            }
            *(float2*)(C + (size_t)row0 * N + col)       = make_float2(v0, v1);
            *(float2*)(C + (size_t)(row0 + 8) * N + col) = make_float2(v2, v3);
        }
    }
}

// ========================= Fused AKT attention, mma.sync version =========================
// Block = (qt, h, b), 256 threads (8 warps), TQ=16 query rows.
// Phase A: S = Q K^T via mma over K chunks of 128 rows (cp.async double-buffered).
// Phase B: softmax -> cumsum -> distance decay -> softmax (warp per 2 rows).
// Phase C: O = P V via mma over V chunks of 128 rows.
#define TQ   16
#define CH   128
#define RP   516            // sRaw pitch (floats)
#define QP   68             // sQ pitch
#define KPP  68             // K tile pitch (phase A)
#define VPP  72             // V tile pitch (phase C)
#define KVBUF (128*72)      // floats per kv buffer
// floats: sRaw 16*516=8256, sQ 16*68=1088, kv 2*9216=18432  -> 27776 floats
#define ATTN_SMEM (27776*(int)sizeof(float))

__global__ __launch_bounds__(256, 2)
void attn_mma(const float* __restrict__ Q, const float* __restrict__ K,
              const float* __restrict__ V, const float* __restrict__ gammas,
              float* __restrict__ O)
{
    extern __shared__ __align__(16) float sm[];
    float* sRaw = sm;                       // 16 x 516
    float* sQ   = sm + 16 * RP;             // 16 x 68
    float* sKV  = sQ + 16 * QP;             // 2 x 128 x 72
    const uint32_t sQa  = smem_to_u32(sQ);
    const uint32_t sKVa = smem_to_u32(sKV);

    const int t    = threadIdx.x;
    const int lane = t & 31, w = t >> 5;
    const int g    = lane >> 2, tg = lane & 3;
    const int qt = blockIdx.x, h = blockIdx.y, b = blockIdx.z;
    const int i0 = qt * TQ;
    const int nch = (i0 + TQ + CH - 1) >> 7;    // chunks of 128 with any valid j

    // init sRaw to masked
    {
        float4 neg = make_float4(-1e32f, -1e32f, -1e32f, -1e32f);
        float4* r4 = (float4*)sRaw;
        for (int idx = t; idx < 16 * RP / 4; idx += 256) r4[idx] = neg;
    }
    // load Q tile (16 x 64) via cp.async, pitch 68
    {
        int r = t >> 4, c4 = t & 15;
        CP_ASYNC16(sQa + (uint32_t)(r * QP + c4 * 4) * 4u,
                   Q + (size_t)(b * SS + i0 + r) * DD + h * 64 + c4 * 4);
    }
    CP_COMMIT();

    // -------- Phase A: scores via mma --------
    // fill K chunk 0 into buffer 0 (pitch 68)
    {
        const float* Kb = K + (size_t)(b * SS) * DD + h * 64;
#pragma unroll
        for (int i = 0; i < 8; i++) {
            int id = t + i * 256;
            int r = id >> 4, c4 = id & 15;
            CP_ASYNC16(sKVa + (uint32_t)(r * KPP + c4 * 4) * 4u,
                       Kb + (size_t)r * DD + c4 * 4);
        }
    }
    CP_COMMIT();

    for (int c = 0; c < nch; c++) {
        CP_WAIT0();
        __syncthreads();
        if (c + 1 < nch) {
            const float* Kb = K + (size_t)(b * SS + (c + 1) * CH) * DD + h * 64;
            const uint32_t dst = sKVa + (uint32_t)(((c + 1) & 1) * KVBUF) * 4u;
#pragma unroll
            for (int i = 0; i < 8; i++) {
                int id = t + i * 256;
                int r = id >> 4, c4 = id & 15;
                CP_ASYNC16(dst + (uint32_t)(r * KPP + c4 * 4) * 4u,
                           Kb + (size_t)r * DD + c4 * 4);
            }
            CP_COMMIT();
        }
        const float* kb = sKV + (c & 1) * KVBUF;

        float acc[2][4] = {{0.f,0.f,0.f,0.f},{0.f,0.f,0.f,0.f}};
#pragma unroll
        for (int k0 = 0; k0 < 64; k0 += 8) {
            uint32_t af[4];
            af[0] = __float_as_uint(sQ[(g    ) * QP + k0 + tg    ]);
            af[1] = __float_as_uint(sQ[(g + 8) * QP + k0 + tg    ]);
            af[2] = __float_as_uint(sQ[(g    ) * QP + k0 + tg + 4]);
            af[3] = __float_as_uint(sQ[(g + 8) * QP + k0 + tg + 4]);
#pragma unroll
            for (int nt = 0; nt < 2; nt++) {
                const int jl = w * 16 + nt * 8 + g;
                uint32_t bf[2];
                bf[0] = __float_as_uint(kb[jl * KPP + k0 + tg    ]);
                bf[1] = __float_as_uint(kb[jl * KPP + k0 + tg + 4]);
                mma_tf32(acc[nt], af, bf);
            }
        }
        // epilogue: mask + scale, write to sRaw
        const int ilo = i0 + g, ihi = i0 + g + 8;
#pragma unroll
        for (int nt = 0; nt < 2; nt++) {
            const int j = c * CH + w * 16 + nt * 8 + 2 * tg;
            sRaw[(g    ) * RP + j    ] = (j     <= ilo) ? acc[nt][0] * 0.125f : -1e32f;
            sRaw[(g    ) * RP + j + 1] = (j + 1 <= ilo) ? acc[nt][1] * 0.125f : -1e32f;
            sRaw[(g + 8) * RP + j    ] = (j     <= ihi) ? acc[nt][2] * 0.125f : -1e32f;
            sRaw[(g + 8) * RP + j + 1] = (j + 1 <= ihi) ? acc[nt][3] * 0.125f : -1e32f;
        }
        __syncthreads();
    }

    // prefetch V chunk 0 (overlap with Phase B); Phase A fully done (last sync above)
    {
        const float* Vb = V + (size_t)(b * SS) * DD + h * 64;
#pragma unroll
        for (int i = 0; i < 8; i++) {
            int id = t + i * 256;
            int r = id >> 4, c4 = id & 15;
            CP_ASYNC16(sKVa + (uint32_t)(r * VPP + c4 * 4) * 4u,
                       Vb + (size_t)r * DD + c4 * 4);
        }
    }
    CP_COMMIT();

    // -------- Phase B: softmax -> cumsum -> decay -> softmax (warp per row) --------
    {
        float gm  = gammas[h];
        float sp  = (gm > 20.f) ? gm : log1pf(expf(gm));
        float gamma = -sp;
#pragma unroll
        for (int rr = 0; rr < 2; rr++) {
            const int row_i = w + rr * 8;
            const int ig = i0 + row_i;
            float* row = sRaw + row_i * RP;
            const float4* rv = (const float4*)row;

            float vals[16];
#pragma unroll
            for (int u = 0; u < 4; u++) {
                float4 v4 = rv[lane * 4 + u];
                vals[4*u+0] = v4.x; vals[4*u+1] = v4.y; vals[4*u+2] = v4.z; vals[4*u+3] = v4.w;
            }

            float mx = -1e32f;
#pragma unroll
            for (int m = 0; m < 16; m++) mx = fmaxf(mx, vals[m]);
#pragma unroll
            for (int off = 16; off > 0; off >>= 1) mx = fmaxf(mx, __shfl_xor_sync(0xffffffffu, mx, off));

            float p[16]; float s = 0.f;
#pragma unroll
            for (int m = 0; m < 16; m++) { p[m] = expf(vals[m] - mx); s += p[m]; }
#pragma unroll
            for (int off = 16; off > 0; off >>= 1) s += __shfl_xor_sync(0xffffffffu, s, off);
            const float inv = 1.f / s;

            float local = 0.f; float cum[16];
#pragma unroll
            for (int m = 0; m < 16; m++) { local += p[m] * inv; cum[m] = local; }
            float run = local;
#pragma unroll
            for (int off = 1; off < 32; off <<= 1) {
                float vv = __shfl_up_sync(0xffffffffu, run, off);
                if (lane >= off) run += vv;
            }
            const float prefix = run - local;
            const float total  = __shfl_sync(0xffffffffu, run, 31);

#pragma unroll
            for (int m = 0; m < 16; m++) {
                int jg = lane * 16 + m;
                float suffix = fmaxf(total - (prefix + cum[m]), 0.f);
                float pe = fabsf((float)(ig - jg));
                float dist = sqrtf(suffix * pe);
                float eff = expf(dist * gamma);
                eff = fminf(fmaxf(eff, 1e-5f), 1e5f);
                vals[m] = vals[m] * eff;
            }

            float mx2 = -1e32f;
#pragma unroll
            for (int m = 0; m < 16; m++) mx2 = fmaxf(mx2, vals[m]);
#pragma unroll
            for (int off = 16; off > 0; off >>= 1) mx2 = fmaxf(mx2, __shfl_xor_sync(0xffffffffu, mx2, off));
            float s2 = 0.f;
#pragma unroll
            for (int m = 0; m < 16; m++) { vals[m] = expf(vals[m] - mx2); s2 += vals[m]; }
#pragma unroll
            for (int off = 16; off > 0; off >>= 1) s2 += __shfl_xor_sync(0xffffffffu, s2, off);
            const float inv2 = 1.f / s2;

            float4* wv = (float4*)row;
#pragma unroll
            for (int u = 0; u < 4; u++) {
                float4 o;
                o.x = vals[4*u+0] * inv2; o.y = vals[4*u+1] * inv2;
                o.z = vals[4*u+2] * inv2; o.w = vals[4*u+3] * inv2;
                wv[lane * 4 + u] = o;
            }
        }
    }
    __syncthreads();

    // -------- Phase C: O = P V via mma --------
    float oc[4] = {0.f, 0.f, 0.f, 0.f};      // warp owns d-cols [w*8, w*8+8)
    for (int c = 0; c < nch; c++) {
        CP_WAIT0();
        __syncthreads();
        if (c + 1 < nch) {
            const float* Vb = V + (size_t)(b * SS + (c + 1) * CH) * DD + h * 64;
            const uint32_t dst = sKVa + (uint32_t)(((c + 1) & 1) * KVBUF) * 4u;
#pragma unroll
            for (int i = 0; i < 8; i++) {
                int id = t + i * 256;
                int r = id >> 4, c4 = id & 15;
                CP_ASYNC16(dst + (uint32_t)(r * VPP + c4 * 4) * 4u,
                           Vb + (size_t)r * DD + c4 * 4);
            }
            CP_COMMIT();
        }
        const float* vb = sKV + (c & 1) * KVBUF;

#pragma unroll
        for (int k0 = 0; k0 < CH; k0 += 8) {
            const int jcol = c * CH + k0 + tg;
            uint32_t af[4];
            af[0] = __float_as_uint(sRaw[(g    ) * RP + jcol    ]);
            af[1] = __float_as_uint(sRaw[(g + 8) * RP + jcol    ]);
            af[2] = __float_as_uint(sRaw[(g    ) * RP + jcol + 4]);
            af[3] = __float_as_uint(sRaw[(g + 8) * RP + jcol + 4]);
            uint32_t bf[2];
            bf[0] = __float_as_uint(vb[(k0 + tg    ) * VPP + w * 8 + g]);
            bf[1] = __float_as_uint(vb[(k0 + tg + 4) * VPP + w * 8 + g]);
            mma_tf32(oc, af, bf);
        }
        __syncthreads();
    }

    const int col = h * 64 + w * 8 + 2 * tg;
    *(float2*)(O + (size_t)(b * SS + i0 + g    ) * DD + col) = make_float2(oc[0], oc[1]);
    *(float2*)(O + (size_t)(b * SS + i0 + g + 8) * DD + col) = make_float2(oc[2], oc[3]);
}

// ---------------- residual add + LayerNorm ----------------
__global__ __launch_bounds__(256)
void add_ln(const float* __restrict__ A, const float* __restrict__ B,
            const float* __restrict__ g, const float* __restrict__ be,
            float* __restrict__ O)
{
    const int row = blockIdx.x;
    const int t = threadIdx.x;
    const float* a = A + (size_t)row * DD;
    const float* b = B + (size_t)row * DD;

    float x0 = a[t] + b[t];
    float x1 = a[t + 256] + b[t + 256];
    float s  = x0 + x1;
    float sq = x0 * x0 + x1 * x1;

    __shared__ float rs[8], rq[8];
    __shared__ float sMu, sRstd;
    const int lane = t & 31, w = t >> 5;
#pragma unroll
    for (int off = 16; off > 0; off >>= 1) {
        s  += __shfl_xor_sync(0xffffffffu, s, off);
        sq += __shfl_xor_sync(0xffffffffu, sq, off);
    }
    if (lane == 0) { rs[w] = s; rq[w] = sq; }
    __syncthreads();
    if (t == 0) {
        float S = 0.f, SQ = 0.f;
#pragma unroll
        for (int i = 0; i < 8; i++) { S += rs[i]; SQ += rq[i]; }
        float mu = S * (1.f / 512.f);
        float var = fmaxf(SQ * (1.f / 512.f) - mu * mu, 0.f);
        sMu = mu;
        sRstd = rsqrtf(var + 1e-5f);
    }
    __syncthreads();
    const float mu = sMu, rstd = sRstd;
    O[(size_t)row * DD + t]       = (x0 - mu) * rstd * g[t]       + be[t];
    O[(size_t)row * DD + t + 256] = (x1 - mu) * rstd * g[t + 256] + be[t + 256];
}

// ---------------- launch ----------------
extern "C" void kernel_launch(void* const* d_in, const int* in_sizes, int n_in,
                              void* d_out, int out_size)
{
    const float* query  = (const float*)d_in[0];
    const float* key    = (const float*)d_in[1];
    const float* values = (const float*)d_in[2];
    const float* Wk     = (const float*)d_in[3];
    const float* bk     = (const float*)d_in[4];
    const float* Wv     = (const float*)d_in[5];
    const float* bv     = (const float*)d_in[6];
    const float* Wo     = (const float*)d_in[7];
    const float* bo     = (const float*)d_in[8];
    const float* gammas = (const float*)d_in[9];
    const float* ln1_g  = (const float*)d_in[10];
    const float* ln1_b  = (const float*)d_in[11];
    const float* W1     = (const float*)d_in[12];
    const float* b1     = (const float*)d_in[13];
    const float* W2     = (const float*)d_in[14];
    const float* b2     = (const float*)d_in[15];
    const float* ln2_g  = (const float*)d_in[16];
    const float* ln2_b  = (const float*)d_in[17];
    float* out = (float*)d_out;

    float *q, *k, *v, *ctx, *ao, *x1, *h1, *f2;
    cudaGetSymbolAddress((void**)&q,   g_q);
    cudaGetSymbolAddress((void**)&k,   g_k);
    cudaGetSymbolAddress((void**)&v,   g_v);
    cudaGetSymbolAddress((void**)&ctx, g_ctx);
    cudaGetSymbolAddress((void**)&ao,  g_ao);
    cudaGetSymbolAddress((void**)&x1,  g_x1);
    cudaGetSymbolAddress((void**)&h1,  g_h1);
    cudaGetSymbolAddress((void**)&f2,  g_f2);

    cudaFuncSetAttribute(attn_mma, cudaFuncAttributeMaxDynamicSharedMemorySize, ATTN_SMEM);
    cudaFuncSetAttribute(gemm_mma<false>, cudaFuncAttributeMaxDynamicSharedMemorySize, GEMM_SMEM);
    cudaFuncSetAttribute(gemm_mma<true>,  cudaFuncAttributeMaxDynamicSharedMemorySize, GEMM_SMEM);

    const dim3 gProj(DD / 128,   MROWS / 128);   // (4, 64)
    const dim3 gFF1 (DFFN / 128, MROWS / 128);   // (16, 64)

    // projections (kq_same=True: q and k both use Wk)
    gemm_mma<false><<<gProj, 256, GEMM_SMEM>>>(query,  Wk, bk, q, MROWS, DD, DD);
    gemm_mma<false><<<gProj, 256, GEMM_SMEM>>>(key,    Wk, bk, k, MROWS, DD, DD);
    gemm_mma<false><<<gProj, 256, GEMM_SMEM>>>(values, Wv, bv, v, MROWS, DD, DD);

    attn_mma<<<dim3(SS / TQ, HH, BB), 256, ATTN_SMEM>>>(q, k, v, gammas, ctx);

    gemm_mma<false><<<gProj, 256, GEMM_SMEM>>>(ctx, Wo, bo, ao, MROWS, DD, DD);

    add_ln<<<MROWS, 256>>>(query, ao, ln1_g, ln1_b, x1);

    gemm_mma<true ><<<gFF1, 256, GEMM_SMEM>>>(x1, W1, b1, h1, MROWS, DFFN, DD);
    gemm_mma<false><<<gProj, 256, GEMM_SMEM>>>(h1, W2, b2, f2, MROWS, DD, DFFN);

    add_ln<<<MROWS, 256>>>(x1, f2, ln2_g, ln2_b, out);
}

// round 6
// speedup vs baseline: 3.6172x; 1.0953x over previous
#include <cuda_runtime.h>
#include <cstdint>
#include <math.h>

// Problem constants
#define BB   16
#define SS   512
#define DD   512
#define HH   8
#define DK   64
#define DFFN 2048
#define MROWS (BB*SS)   // 8192

// ---------------- scratch (static device globals; no allocation) ----------------
__device__ float g_q  [MROWS*DD];
__device__ float g_k  [MROWS*DD];
__device__ float g_v  [MROWS*DD];
__device__ float g_ctx[MROWS*DD];
__device__ float g_ao [MROWS*DD];
__device__ float g_x1 [MROWS*DD];
__device__ float g_h1 [MROWS*DFFN];
__device__ float g_f2 [MROWS*DD];

// ---------------- helpers ----------------
__device__ __forceinline__ uint32_t smem_to_u32(const void* p) {
    uint32_t a;
    asm("{ .reg .u64 tmp; cvta.to.shared.u64 tmp, %1; cvt.u32.u64 %0, tmp; }" : "=r"(a) : "l"(p));
    return a;
}
#define CP_ASYNC16(saddr, gptr) \
    asm volatile("cp.async.cg.shared.global [%0], [%1], 16;" :: "r"(saddr), "l"(gptr))
#define CP_COMMIT() asm volatile("cp.async.commit_group;" ::: "memory")
#define CP_WAIT0()  asm volatile("cp.async.wait_group 0;" ::: "memory")

// mma.sync m16n8k8 tf32 (A row-major, B col-major, fp32 accum)
__device__ __forceinline__ void mma_tf32(float* c, const uint32_t* a, const uint32_t* b) {
    asm volatile(
        "mma.sync.aligned.m16n8k8.row.col.f32.tf32.tf32.f32 "
        "{%0,%1,%2,%3}, {%4,%5,%6,%7}, {%8,%9}, {%0,%1,%2,%3};"
        : "+f"(c[0]), "+f"(c[1]), "+f"(c[2]), "+f"(c[3])
        : "r"(a[0]), "r"(a[1]), "r"(a[2]), "r"(a[3]), "r"(b[0]), "r"(b[1]));
}

// fast exp / sqrt via MUFU (precision ~2^-21 rel — far below tf32 noise)
__device__ __forceinline__ float fexp(float x) {
    float y;
    asm("ex2.approx.f32 %0, %1;" : "=f"(y) : "f"(x * 1.4426950408889634f));
    return y;
}
__device__ __forceinline__ float fsqrt_ap(float x) {
    float y;
    asm("sqrt.approx.f32 %0, %1;" : "=f"(y) : "f"(x));
    return y;
}

// ========================= tf32 mma.sync GEMM =========================
#define AP 36
#define BP 132
#define A_TILE (128*AP)
#define B_TILE (32*BP)
#define GEMM_BUF (A_TILE + B_TILE)
#define GEMM_SMEM (2*GEMM_BUF*(int)sizeof(float))

__device__ __forceinline__ void fill_tiles(const float* __restrict__ A,
                                           const float* __restrict__ W,
                                           int K, int N, int bm, int bn, int kc,
                                           uint32_t sA, uint32_t sB, int t)
{
#pragma unroll
    for (int i = 0; i < 4; i++) {
        int id  = t + i * 256;
        int row = id >> 3, k4 = id & 7;
        const float* src = A + (size_t)(bm + row) * K + kc * 32 + k4 * 4;
        CP_ASYNC16(sA + (uint32_t)(row * AP + k4 * 4) * 4u, src);
    }
#pragma unroll
    for (int i = 0; i < 4; i++) {
        int id   = t + i * 256;
        int krow = id >> 5, n4 = id & 31;
        const float* src = W + (size_t)(kc * 32 + krow) * N + bn + n4 * 4;
        CP_ASYNC16(sB + (uint32_t)(krow * BP + n4 * 4) * 4u, src);
    }
}

template<bool RELU>
__device__ __forceinline__ void gemm_body(const float* __restrict__ A,
                                          const float* __restrict__ W,
                                          const float* __restrict__ bias,
                                          float* __restrict__ C,
                                          int N, int K, int bm, int bn,
                                          float* smem_g)
{
    const int t    = threadIdx.x;
    const int lane = t & 31, wid = t >> 5;
    const int g    = lane >> 2, tg = lane & 3;
    const int wm   = (wid >> 2) * 64;
    const int wn   = (wid & 3) * 32;
    const uint32_t sbase = smem_to_u32(smem_g);

    float acc[4][4][4];
#pragma unroll
    for (int mt = 0; mt < 4; mt++)
#pragma unroll
        for (int nt = 0; nt < 4; nt++)
#pragma unroll
            for (int r = 0; r < 4; r++) acc[mt][nt][r] = 0.f;

    const int nk = K >> 5;

    fill_tiles(A, W, K, N, bm, bn, 0, sbase, sbase + A_TILE * 4, t);
    CP_COMMIT();

    for (int kc = 0; kc < nk; kc++) {
        CP_WAIT0();
        __syncthreads();
        if (kc + 1 < nk) {
            const uint32_t off = ((kc + 1) & 1) * (uint32_t)(GEMM_BUF * 4);
            fill_tiles(A, W, K, N, bm, bn, kc + 1, sbase + off, sbase + off + A_TILE * 4, t);
            CP_COMMIT();
        }
        const float* aS = smem_g + (kc & 1) * GEMM_BUF;
        const float* bS = aS + A_TILE;

#pragma unroll
        for (int ks = 0; ks < 4; ks++) {
            const int k0 = ks * 8;
            uint32_t af[4][4];
#pragma unroll
            for (int mt = 0; mt < 4; mt++) {
                const int mrow = wm + mt * 16 + g;
                af[mt][0] = __float_as_uint(aS[(mrow    ) * AP + k0 + tg    ]);
                af[mt][1] = __float_as_uint(aS[(mrow + 8) * AP + k0 + tg    ]);
                af[mt][2] = __float_as_uint(aS[(mrow    ) * AP + k0 + tg + 4]);
                af[mt][3] = __float_as_uint(aS[(mrow + 8) * AP + k0 + tg + 4]);
            }
            uint32_t bf[4][2];
#pragma unroll
            for (int nt = 0; nt < 4; nt++) {
                const int ncol = wn + nt * 8 + g;
                bf[nt][0] = __float_as_uint(bS[(k0 + tg    ) * BP + ncol]);
                bf[nt][1] = __float_as_uint(bS[(k0 + tg + 4) * BP + ncol]);
            }
#pragma unroll
            for (int mt = 0; mt < 4; mt++)
#pragma unroll
                for (int nt = 0; nt < 4; nt++)
                    mma_tf32(acc[mt][nt], af[mt], bf[nt]);
        }
    }

#pragma unroll
    for (int mt = 0; mt < 4; mt++) {
#pragma unroll
        for (int nt = 0; nt < 4; nt++) {
            const int row0 = bm + wm + mt * 16 + g;
            const int col  = bn + wn + nt * 8 + 2 * tg;
            float b0 = bias[col], b1 = bias[col + 1];
            float v0 = acc[mt][nt][0] + b0, v1 = acc[mt][nt][1] + b1;
            float v2 = acc[mt][nt][2] + b0, v3 = acc[mt][nt][3] + b1;
            if (RELU) {
                v0 = fmaxf(v0, 0.f); v1 = fmaxf(v1, 0.f);
                v2 = fmaxf(v2, 0.f); v3 = fmaxf(v3, 0.f);
            }
            *(float2*)(C + (size_t)row0 * N + col)       = make_float2(v0, v1);
            *(float2*)(C + (size_t)(row0 + 8) * N + col) = make_float2(v2, v3);
        }
    }
}

template<bool RELU>
__global__ __launch_bounds__(256, 2)
void gemm_mma(const float* __restrict__ A, const float* __restrict__ W,
              const float* __restrict__ bias, float* __restrict__ C,
              int M, int N, int K)
{
    extern __shared__ __align__(16) float smem_g[];
    gemm_body<RELU>(A, W, bias, C, N, K, blockIdx.y * 128, blockIdx.x * 128, smem_g);
}

// batched projections: z selects (query->q | key->k | values->v); q,k share Wk/bk
__global__ __launch_bounds__(256, 2)
void gemm_proj3(const float* __restrict__ A0, const float* __restrict__ A1,
                const float* __restrict__ A2,
                const float* __restrict__ Wk, const float* __restrict__ Wv,
                const float* __restrict__ bk, const float* __restrict__ bv,
                float* __restrict__ C0, float* __restrict__ C1, float* __restrict__ C2)
{
    extern __shared__ __align__(16) float smem_g[];
    const int z = blockIdx.z;
    const float* A = (z == 0) ? A0 : (z == 1) ? A1 : A2;
    const float* W = (z == 2) ? Wv : Wk;
    const float* bias = (z == 2) ? bv : bk;
    float* C = (z == 0) ? C0 : (z == 1) ? C1 : C2;
    gemm_body<false>(A, W, bias, C, DD, DD, blockIdx.y * 128, blockIdx.x * 128, smem_g);
}

// ========================= Fused AKT attention, mma.sync =========================
#define TQ   16
#define CH   128
#define RP   516
#define QP   68
#define KPP  68
#define VPP  72
#define KVBUF (128*72)
#define ATTN_SMEM (27776*(int)sizeof(float))

__global__ __launch_bounds__(256, 2)
void attn_mma(const float* __restrict__ Q, const float* __restrict__ K,
              const float* __restrict__ V, const float* __restrict__ gammas,
              float* __restrict__ O)
{
    extern __shared__ __align__(16) float sm[];
    float* sRaw = sm;                       // 16 x 516
    float* sQ   = sm + 16 * RP;             // 16 x 68
    float* sKV  = sQ + 16 * QP;             // 2 x 128 x 72
    const uint32_t sQa  = smem_to_u32(sQ);
    const uint32_t sKVa = smem_to_u32(sKV);

    const int t    = threadIdx.x;
    const int lane = t & 31, w = t >> 5;
    const int g    = lane >> 2, tg = lane & 3;
    const int qt = blockIdx.x, h = blockIdx.y, b = blockIdx.z;
    const int i0 = qt * TQ;
    const int nch = (i0 + TQ + CH - 1) >> 7;

    // load Q tile (16 x 64) via cp.async, pitch 68
    {
        int r = t >> 4, c4 = t & 15;
        CP_ASYNC16(sQa + (uint32_t)(r * QP + c4 * 4) * 4u,
                   Q + (size_t)(b * SS + i0 + r) * DD + h * 64 + c4 * 4);
    }
    CP_COMMIT();

    // init only the tail region Phase A never writes: cols [nch*CH, 512)
    {
        const int j0i = nch * CH;
        const int nf4 = (512 - j0i) >> 2;
        if (nf4 > 0) {
            for (int idx = t; idx < 16 * nf4; idx += 256) {
                int r = idx / nf4, c = idx - r * nf4;
                *(float4*)(sRaw + r * RP + j0i + c * 4) =
                    make_float4(-1e32f, -1e32f, -1e32f, -1e32f);
            }
        }
    }

    // -------- Phase A: scores via mma --------
    {
        const float* Kb = K + (size_t)(b * SS) * DD + h * 64;
#pragma unroll
        for (int i = 0; i < 8; i++) {
            int id = t + i * 256;
            int r = id >> 4, c4 = id & 15;
            CP_ASYNC16(sKVa + (uint32_t)(r * KPP + c4 * 4) * 4u,
                       Kb + (size_t)r * DD + c4 * 4);
        }
    }
    CP_COMMIT();

    for (int c = 0; c < nch; c++) {
        CP_WAIT0();
        __syncthreads();
        if (c + 1 < nch) {
            const float* Kb = K + (size_t)(b * SS + (c + 1) * CH) * DD + h * 64;
            const uint32_t dst = sKVa + (uint32_t)(((c + 1) & 1) * KVBUF) * 4u;
#pragma unroll
            for (int i = 0; i < 8; i++) {
                int id = t + i * 256;
                int r = id >> 4, c4 = id & 15;
                CP_ASYNC16(dst + (uint32_t)(r * KPP + c4 * 4) * 4u,
                           Kb + (size_t)r * DD + c4 * 4);
            }
            CP_COMMIT();
        }
        const float* kb = sKV + (c & 1) * KVBUF;

        float acc[2][4] = {{0.f,0.f,0.f,0.f},{0.f,0.f,0.f,0.f}};
#pragma unroll
        for (int k0 = 0; k0 < 64; k0 += 8) {
            uint32_t af[4];
            af[0] = __float_as_uint(sQ[(g    ) * QP + k0 + tg    ]);
            af[1] = __float_as_uint(sQ[(g + 8) * QP + k0 + tg    ]);
            af[2] = __float_as_uint(sQ[(g    ) * QP + k0 + tg + 4]);
            af[3] = __float_as_uint(sQ[(g + 8) * QP + k0 + tg + 4]);
#pragma unroll
            for (int nt = 0; nt < 2; nt++) {
                const int jl = w * 16 + nt * 8 + g;
                uint32_t bf[2];
                bf[0] = __float_as_uint(kb[jl * KPP + k0 + tg    ]);
                bf[1] = __float_as_uint(kb[jl * KPP + k0 + tg + 4]);
                mma_tf32(acc[nt], af, bf);
            }
        }
        const int ilo = i0 + g, ihi = i0 + g + 8;
#pragma unroll
        for (int nt = 0; nt < 2; nt++) {
            const int j = c * CH + w * 16 + nt * 8 + 2 * tg;
            sRaw[(g    ) * RP + j    ] = (j     <= ilo) ? acc[nt][0] * 0.125f : -1e32f;
            sRaw[(g    ) * RP + j + 1] = (j + 1 <= ilo) ? acc[nt][1] * 0.125f : -1e32f;
            sRaw[(g + 8) * RP + j    ] = (j     <= ihi) ? acc[nt][2] * 0.125f : -1e32f;
            sRaw[(g + 8) * RP + j + 1] = (j + 1 <= ihi) ? acc[nt][3] * 0.125f : -1e32f;
        }
        __syncthreads();
    }

    // prefetch V chunk 0 (overlaps Phase B)
    {
        const float* Vb = V + (size_t)(b * SS) * DD + h * 64;
#pragma unroll
        for (int i = 0; i < 8; i++) {
            int id = t + i * 256;
            int r = id >> 4, c4 = id & 15;
            CP_ASYNC16(sKVa + (uint32_t)(r * VPP + c4 * 4) * 4u,
                       Vb + (size_t)r * DD + c4 * 4);
        }
    }
    CP_COMMIT();

    // -------- Phase B: softmax -> cumsum -> decay -> softmax (warp per row) --------
    {
        float gm  = gammas[h];
        float sp  = (gm > 20.f) ? gm : log1pf(expf(gm));
        float gamma = -sp;
#pragma unroll
        for (int rr = 0; rr < 2; rr++) {
            const int row_i = w + rr * 8;
            const int ig = i0 + row_i;
            float* row = sRaw + row_i * RP;
            const float4* rv = (const float4*)row;

            float vals[16];
#pragma unroll
            for (int u = 0; u < 4; u++) {
                float4 v4 = rv[lane * 4 + u];
                vals[4*u+0] = v4.x; vals[4*u+1] = v4.y; vals[4*u+2] = v4.z; vals[4*u+3] = v4.w;
            }

            float mx = -1e32f;
#pragma unroll
            for (int m = 0; m < 16; m++) mx = fmaxf(mx, vals[m]);
#pragma unroll
            for (int off = 16; off > 0; off >>= 1) mx = fmaxf(mx, __shfl_xor_sync(0xffffffffu, mx, off));

            float p[16]; float s = 0.f;
#pragma unroll
            for (int m = 0; m < 16; m++) { p[m] = fexp(vals[m] - mx); s += p[m]; }
#pragma unroll
            for (int off = 16; off > 0; off >>= 1) s += __shfl_xor_sync(0xffffffffu, s, off);
            const float inv = 1.f / s;

            float local = 0.f; float cum[16];
#pragma unroll
            for (int m = 0; m < 16; m++) { local += p[m] * inv; cum[m] = local; }
            float run = local;
#pragma unroll
            for (int off = 1; off < 32; off <<= 1) {
                float vv = __shfl_up_sync(0xffffffffu, run, off);
                if (lane >= off) run += vv;
            }
            const float prefix = run - local;
            const float total  = __shfl_sync(0xffffffffu, run, 31);

#pragma unroll
            for (int m = 0; m < 16; m++) {
                int jg = lane * 16 + m;
                float suffix = fmaxf(total - (prefix + cum[m]), 0.f);
                float pe = fabsf((float)(ig - jg));
                float dist = fsqrt_ap(suffix * pe);
                float eff = fexp(dist * gamma);
                eff = fminf(fmaxf(eff, 1e-5f), 1e5f);
                vals[m] = vals[m] * eff;
            }

            float mx2 = -1e32f;
#pragma unroll
            for (int m = 0; m < 16; m++) mx2 = fmaxf(mx2, vals[m]);
#pragma unroll
            for (int off = 16; off > 0; off >>= 1) mx2 = fmaxf(mx2, __shfl_xor_sync(0xffffffffu, mx2, off));
            float s2 = 0.f;
#pragma unroll
            for (int m = 0; m < 16; m++) { vals[m] = fexp(vals[m] - mx2); s2 += vals[m]; }
#pragma unroll
            for (int off = 16; off > 0; off >>= 1) s2 += __shfl_xor_sync(0xffffffffu, s2, off);
            const float inv2 = 1.f / s2;

            float4* wv = (float4*)row;
#pragma unroll
            for (int u = 0; u < 4; u++) {
                float4 o;
                o.x = vals[4*u+0] * inv2; o.y = vals[4*u+1] * inv2;
                o.z = vals[4*u+2] * inv2; o.w = vals[4*u+3] * inv2;
                wv[lane * 4 + u] = o;
            }
        }
    }
    __syncthreads();

    // -------- Phase C: O = P V via mma --------
    float oc[4] = {0.f, 0.f, 0.f, 0.f};
    for (int c = 0; c < nch; c++) {
        CP_WAIT0();
        __syncthreads();
        if (c + 1 < nch) {
            const float* Vb = V + (size_t)(b * SS + (c + 1) * CH) * DD + h * 64;
            const uint32_t dst = sKVa + (uint32_t)(((c + 1) & 1) * KVBUF) * 4u;
#pragma unroll
            for (int i = 0; i < 8; i++) {
                int id = t + i * 256;
                int r = id >> 4, c4 = id & 15;
                CP_ASYNC16(dst + (uint32_t)(r * VPP + c4 * 4) * 4u,
                           Vb + (size_t)r * DD + c4 * 4);
            }
            CP_COMMIT();
        }
        const float* vb = sKV + (c & 1) * KVBUF;

#pragma unroll
        for (int k0 = 0; k0 < CH; k0 += 8) {
            const int jcol = c * CH + k0 + tg;
            uint32_t af[4];
            af[0] = __float_as_uint(sRaw[(g    ) * RP + jcol    ]);
            af[1] = __float_as_uint(sRaw[(g + 8) * RP + jcol    ]);
            af[2] = __float_as_uint(sRaw[(g    ) * RP + jcol + 4]);
            af[3] = __float_as_uint(sRaw[(g + 8) * RP + jcol + 4]);
            uint32_t bf[2];
            bf[0] = __float_as_uint(vb[(k0 + tg    ) * VPP + w * 8 + g]);
            bf[1] = __float_as_uint(vb[(k0 + tg + 4) * VPP + w * 8 + g]);
            mma_tf32(oc, af, bf);
        }
        __syncthreads();
    }

    const int col = h * 64 + w * 8 + 2 * tg;
    *(float2*)(O + (size_t)(b * SS + i0 + g    ) * DD + col) = make_float2(oc[0], oc[1]);
    *(float2*)(O + (size_t)(b * SS + i0 + g + 8) * DD + col) = make_float2(oc[2], oc[3]);
}

// ---------------- residual add + LayerNorm ----------------
__global__ __launch_bounds__(256)
void add_ln(const float* __restrict__ A, const float* __restrict__ B,
            const float* __restrict__ g, const float* __restrict__ be,
            float* __restrict__ O)
{
    const int row = blockIdx.x;
    const int t = threadIdx.x;
    const float* a = A + (size_t)row * DD;
    const float* b = B + (size_t)row * DD;

    float x0 = a[t] + b[t];
    float x1 = a[t + 256] + b[t + 256];
    float s  = x0 + x1;
    float sq = x0 * x0 + x1 * x1;

    __shared__ float rs[8], rq[8];
    __shared__ float sMu, sRstd;
    const int lane = t & 31, w = t >> 5;
#pragma unroll
    for (int off = 16; off > 0; off >>= 1) {
        s  += __shfl_xor_sync(0xffffffffu, s, off);
        sq += __shfl_xor_sync(0xffffffffu, sq, off);
    }
    if (lane == 0) { rs[w] = s; rq[w] = sq; }
    __syncthreads();
    if (t == 0) {
        float S = 0.f, SQ = 0.f;
#pragma unroll
        for (int i = 0; i < 8; i++) { S += rs[i]; SQ += rq[i]; }
        float mu = S * (1.f / 512.f);
        float var = fmaxf(SQ * (1.f / 512.f) - mu * mu, 0.f);
        sMu = mu;
        sRstd = rsqrtf(var + 1e-5f);
    }
    __syncthreads();
    const float mu = sMu, rstd = sRstd;
    O[(size_t)row * DD + t]       = (x0 - mu) * rstd * g[t]       + be[t];
    O[(size_t)row * DD + t + 256] = (x1 - mu) * rstd * g[t + 256] + be[t + 256];
}

// ---------------- launch ----------------
extern "C" void kernel_launch(void* const* d_in, const int* in_sizes, int n_in,
                              void* d_out, int out_size)
{
    const float* query  = (const float*)d_in[0];
    const float* key    = (const float*)d_in[1];
    const float* values = (const float*)d_in[2];
    const float* Wk     = (const float*)d_in[3];
    const float* bk     = (const float*)d_in[4];
    const float* Wv     = (const float*)d_in[5];
    const float* bv     = (const float*)d_in[6];
    const float* Wo     = (const float*)d_in[7];
    const float* bo     = (const float*)d_in[8];
    const float* gammas = (const float*)d_in[9];
    const float* ln1_g  = (const float*)d_in[10];
    const float* ln1_b  = (const float*)d_in[11];
    const float* W1     = (const float*)d_in[12];
    const float* b1     = (const float*)d_in[13];
    const float* W2     = (const float*)d_in[14];
    const float* b2     = (const float*)d_in[15];
    const float* ln2_g  = (const float*)d_in[16];
    const float* ln2_b  = (const float*)d_in[17];
    float* out = (float*)d_out;

    float *q, *k, *v, *ctx, *ao, *x1, *h1, *f2;
    cudaGetSymbolAddress((void**)&q,   g_q);
    cudaGetSymbolAddress((void**)&k,   g_k);
    cudaGetSymbolAddress((void**)&v,   g_v);
    cudaGetSymbolAddress((void**)&ctx, g_ctx);
    cudaGetSymbolAddress((void**)&ao,  g_ao);
    cudaGetSymbolAddress((void**)&x1,  g_x1);
    cudaGetSymbolAddress((void**)&h1,  g_h1);
    cudaGetSymbolAddress((void**)&f2,  g_f2);

    cudaFuncSetAttribute(attn_mma, cudaFuncAttributeMaxDynamicSharedMemorySize, ATTN_SMEM);
    cudaFuncSetAttribute(gemm_mma<false>, cudaFuncAttributeMaxDynamicSharedMemorySize, GEMM_SMEM);
    cudaFuncSetAttribute(gemm_mma<true>,  cudaFuncAttributeMaxDynamicSharedMemorySize, GEMM_SMEM);
    cudaFuncSetAttribute(gemm_proj3,      cudaFuncAttributeMaxDynamicSharedMemorySize, GEMM_SMEM);

    const dim3 gProj (DD / 128,   MROWS / 128);     // (4, 64)
    const dim3 gProj3(DD / 128,   MROWS / 128, 3);  // batched q/k/v
    const dim3 gFF1  (DFFN / 128, MROWS / 128);     // (16, 64)

    // batched projections (kq_same=True: q and k both use Wk)
    gemm_proj3<<<gProj3, 256, GEMM_SMEM>>>(query, key, values, Wk, Wv, bk, bv, q, k, v);

    attn_mma<<<dim3(SS / TQ, HH, BB), 256, ATTN_SMEM>>>(q, k, v, gammas, ctx);

    gemm_mma<false><<<gProj, 256, GEMM_SMEM>>>(ctx, Wo, bo, ao, MROWS, DD, DD);

    add_ln<<<MROWS, 256>>>(query, ao, ln1_g, ln1_b, x1);

    gemm_mma<true ><<<gFF1, 256, GEMM_SMEM>>>(x1, W1, b1, h1, MROWS, DFFN, DD);
    gemm_mma<false><<<gProj, 256, GEMM_SMEM>>>(h1, W2, b2, f2, MROWS, DD, DFFN);

    add_ln<<<MROWS, 256>>>(x1, f2, ln2_g, ln2_b, out);
}

// round 7
// speedup vs baseline: 5.0889x; 1.4069x over previous
#include <cuda_runtime.h>
#include <cuda_fp16.h>
#include <cstdint>
#include <math.h>

// Problem constants
#define BB   16
#define SS   512
#define DD   512
#define HH   8
#define DK   64
#define DFFN 2048
#define MROWS (BB*SS)   // 8192

// ---------------- scratch (static device globals; no allocation) ----------------
__device__ float g_q  [MROWS*DD];
__device__ float g_k  [MROWS*DD];
__device__ float g_v  [MROWS*DD];
__device__ float g_ao [MROWS*DD];
__device__ float g_x1 [MROWS*DD];
__device__ float g_f2 [MROWS*DD];
// fp16 activations
__device__ __half g_in16q[MROWS*DD];
__device__ __half g_in16k[MROWS*DD];
__device__ __half g_in16v[MROWS*DD];
__device__ __half g_ctx16[MROWS*DD];
__device__ __half g_x116 [MROWS*DD];
__device__ __half g_h116 [MROWS*DFFN];
// fp16 transposed weights [N][K]
__device__ __half g_wkT16[DD*DD];
__device__ __half g_wvT16[DD*DD];
__device__ __half g_woT16[DD*DD];
__device__ __half g_w1T16[DFFN*DD];
__device__ __half g_w2T16[DD*DFFN];

// ---------------- helpers ----------------
__device__ __forceinline__ uint32_t smem_to_u32(const void* p) {
    uint32_t a;
    asm("{ .reg .u64 tmp; cvta.to.shared.u64 tmp, %1; cvt.u32.u64 %0, tmp; }" : "=r"(a) : "l"(p));
    return a;
}
#define CP_ASYNC16(saddr, gptr) \
    asm volatile("cp.async.cg.shared.global [%0], [%1], 16;" :: "r"(saddr), "l"(gptr))
#define CP_COMMIT() asm volatile("cp.async.commit_group;" ::: "memory")
#define CP_WAIT0()  asm volatile("cp.async.wait_group 0;" ::: "memory")
#define CP_WAIT1()  asm volatile("cp.async.wait_group 1;" ::: "memory")

// mma m16n8k8 tf32 (attention)
__device__ __forceinline__ void mma_tf32(float* c, const uint32_t* a, const uint32_t* b) {
    asm volatile(
        "mma.sync.aligned.m16n8k8.row.col.f32.tf32.tf32.f32 "
        "{%0,%1,%2,%3}, {%4,%5,%6,%7}, {%8,%9}, {%0,%1,%2,%3};"
        : "+f"(c[0]), "+f"(c[1]), "+f"(c[2]), "+f"(c[3])
        : "r"(a[0]), "r"(a[1]), "r"(a[2]), "r"(a[3]), "r"(b[0]), "r"(b[1]));
}
// mma m16n8k16 fp16, fp32 accumulate (GEMMs)
__device__ __forceinline__ void mma_f16(float* c, const uint32_t* a, const uint32_t* b) {
    asm volatile(
        "mma.sync.aligned.m16n8k16.row.col.f32.f16.f16.f32 "
        "{%0,%1,%2,%3}, {%4,%5,%6,%7}, {%8,%9}, {%0,%1,%2,%3};"
        : "+f"(c[0]), "+f"(c[1]), "+f"(c[2]), "+f"(c[3])
        : "r"(a[0]), "r"(a[1]), "r"(a[2]), "r"(a[3]), "r"(b[0]), "r"(b[1]));
}

__device__ __forceinline__ float fexp(float x) {
    float y;
    asm("ex2.approx.f32 %0, %1;" : "=f"(y) : "f"(x * 1.4426950408889634f));
    return y;
}
__device__ __forceinline__ float fsqrt_ap(float x) {
    float y;
    asm("sqrt.approx.f32 %0, %1;" : "=f"(y) : "f"(x));
    return y;
}

// ========================= fp16 mma GEMM =========================
// C[M,N] = A[M,K] @ Bt[N,K]^T + bias.  A, Bt fp16 (both [rows][K] k-contiguous).
// 128x128 tile, BK=64, 256 threads = 8 warps (2m x 4n), double-buffered cp.async.
#define HP 72                          // smem pitch in halves
#define TILE_H (128*HP)                // halves per tile
#define STAGE_H (2*TILE_H)             // A+B per stage
#define GEMM_H_SMEM (2*STAGE_H*(int)sizeof(__half))   // 73728 B

__device__ __forceinline__ void fill_h(const __half* __restrict__ A,
                                       const __half* __restrict__ Bt,
                                       int K, int bm, int bn, int kc,
                                       uint32_t sA, uint32_t sB, int t)
{
#pragma unroll
    for (int i = 0; i < 4; i++) {
        int id = t + i * 256;
        int row = id >> 3, c = id & 7;
        CP_ASYNC16(sA + (uint32_t)(row * HP + c * 8) * 2u,
                   A + (size_t)(bm + row) * K + kc * 64 + c * 8);
    }
#pragma unroll
    for (int i = 0; i < 4; i++) {
        int id = t + i * 256;
        int row = id >> 3, c = id & 7;
        CP_ASYNC16(sB + (uint32_t)(row * HP + c * 8) * 2u,
                   Bt + (size_t)(bn + row) * K + kc * 64 + c * 8);
    }
}

template<bool RELU, bool OUT16>
__device__ __forceinline__ void gemm_h_body(const __half* __restrict__ A,
                                            const __half* __restrict__ Bt,
                                            const float* __restrict__ bias,
                                            float* __restrict__ C,
                                            __half* __restrict__ C16,
                                            int N, int K, int bm, int bn,
                                            __half* smem_h)
{
    const int t    = threadIdx.x;
    const int lane = t & 31, wid = t >> 5;
    const int g    = lane >> 2, tg = lane & 3;
    const int wm   = (wid >> 2) * 64;
    const int wn   = (wid & 3) * 32;
    const uint32_t sbase = smem_to_u32(smem_h);

    float acc[4][4][4];
#pragma unroll
    for (int mt = 0; mt < 4; mt++)
#pragma unroll
        for (int nt = 0; nt < 4; nt++)
#pragma unroll
            for (int r = 0; r < 4; r++) acc[mt][nt][r] = 0.f;

    const int nk = K >> 6;

    fill_h(A, Bt, K, bm, bn, 0, sbase, sbase + TILE_H * 2, t);
    CP_COMMIT();

    for (int kc = 0; kc < nk; kc++) {
        CP_WAIT0();
        __syncthreads();
        if (kc + 1 < nk) {
            const uint32_t off = ((kc + 1) & 1) * (uint32_t)(STAGE_H * 2);
            fill_h(A, Bt, K, bm, bn, kc + 1, sbase + off, sbase + off + TILE_H * 2, t);
            CP_COMMIT();
        }
        const __half* aS = smem_h + (kc & 1) * STAGE_H;
        const __half* bS = aS + TILE_H;

#pragma unroll
        for (int ks = 0; ks < 4; ks++) {
            const int k0 = ks * 16;
            uint32_t af[4][4];
#pragma unroll
            for (int mt = 0; mt < 4; mt++) {
                const int mrow = wm + mt * 16 + g;
                af[mt][0] = *(const uint32_t*)(aS + mrow * HP + k0 + 2 * tg);
                af[mt][1] = *(const uint32_t*)(aS + (mrow + 8) * HP + k0 + 2 * tg);
                af[mt][2] = *(const uint32_t*)(aS + mrow * HP + k0 + 2 * tg + 8);
                af[mt][3] = *(const uint32_t*)(aS + (mrow + 8) * HP + k0 + 2 * tg + 8);
            }
            uint32_t bf[4][2];
#pragma unroll
            for (int nt = 0; nt < 4; nt++) {
                const int ncol = wn + nt * 8 + g;
                bf[nt][0] = *(const uint32_t*)(bS + ncol * HP + k0 + 2 * tg);
                bf[nt][1] = *(const uint32_t*)(bS + ncol * HP + k0 + 2 * tg + 8);
            }
#pragma unroll
            for (int mt = 0; mt < 4; mt++)
#pragma unroll
                for (int nt = 0; nt < 4; nt++)
                    mma_f16(acc[mt][nt], af[mt], bf[nt]);
        }
    }

#pragma unroll
    for (int mt = 0; mt < 4; mt++) {
#pragma unroll
        for (int nt = 0; nt < 4; nt++) {
            const int row0 = bm + wm + mt * 16 + g;
            const int col  = bn + wn + nt * 8 + 2 * tg;
            float b0 = bias[col], b1 = bias[col + 1];
            float v0 = acc[mt][nt][0] + b0, v1 = acc[mt][nt][1] + b1;
            float v2 = acc[mt][nt][2] + b0, v3 = acc[mt][nt][3] + b1;
            if (RELU) {
                v0 = fmaxf(v0, 0.f); v1 = fmaxf(v1, 0.f);
                v2 = fmaxf(v2, 0.f); v3 = fmaxf(v3, 0.f);
            }
            if (OUT16) {
                *(__half2*)(C16 + (size_t)row0 * N + col)       = __floats2half2_rn(v0, v1);
                *(__half2*)(C16 + (size_t)(row0 + 8) * N + col) = __floats2half2_rn(v2, v3);
            } else {
                *(float2*)(C + (size_t)row0 * N + col)       = make_float2(v0, v1);
                *(float2*)(C + (size_t)(row0 + 8) * N + col) = make_float2(v2, v3);
            }
        }
    }
}

template<bool RELU, bool OUT16>
__global__ __launch_bounds__(256, 2)
void gemm_h(const __half* __restrict__ A, const __half* __restrict__ Bt,
            const float* __restrict__ bias, float* __restrict__ C,
            __half* __restrict__ C16, int M, int N, int K)
{
    extern __shared__ __align__(16) __half smem_h[];
    gemm_h_body<RELU, OUT16>(A, Bt, bias, C, C16, N, K,
                             blockIdx.y * 128, blockIdx.x * 128, smem_h);
}

// batched q/k/v projections (fp16 in, fp32 out); q,k share Wk/bk
__global__ __launch_bounds__(256, 2)
void gemm_proj3_h(const __half* __restrict__ A0, const __half* __restrict__ A1,
                  const __half* __restrict__ A2,
                  const __half* __restrict__ WkT, const __half* __restrict__ WvT,
                  const float* __restrict__ bk, const float* __restrict__ bv,
                  float* __restrict__ C0, float* __restrict__ C1, float* __restrict__ C2)
{
    extern __shared__ __align__(16) __half smem_h[];
    const int z = blockIdx.z;
    const __half* A = (z == 0) ? A0 : (z == 1) ? A1 : A2;
    const __half* W = (z == 2) ? WvT : WkT;
    const float* bias = (z == 2) ? bv : bk;
    float* C = (z == 0) ? C0 : (z == 1) ? C1 : C2;
    gemm_h_body<false, false>(A, W, bias, C, ((__half*)0), DD, DD,
                              blockIdx.y * 128, blockIdx.x * 128, smem_h);
}

// ---------------- prep kernels ----------------
__global__ __launch_bounds__(256)
void conv_fp16_3(const float* __restrict__ s0, const float* __restrict__ s1,
                 const float* __restrict__ s2,
                 __half* __restrict__ d0, __half* __restrict__ d1, __half* __restrict__ d2)
{
    const int z = blockIdx.z;
    const float* s = (z == 0) ? s0 : (z == 1) ? s1 : s2;
    __half* d = (z == 0) ? d0 : (z == 1) ? d1 : d2;
    const int n4 = MROWS * DD / 4;
    for (int i = blockIdx.x * 256 + threadIdx.x; i < n4; i += gridDim.x * 256) {
        float4 v = ((const float4*)s)[i];
        ((__half2*)d)[2 * i    ] = __floats2half2_rn(v.x, v.y);
        ((__half2*)d)[2 * i + 1] = __floats2half2_rn(v.z, v.w);
    }
}

__global__ __launch_bounds__(256)
void transpose_h(const float* __restrict__ in, __half* __restrict__ out, int R, int C)
{
    __shared__ float tile[32][33];
    const int bx = blockIdx.x * 32;   // col base
    const int by = blockIdx.y * 32;   // row base
    const int tx = threadIdx.x & 31;
    const int ty = threadIdx.x >> 5;
#pragma unroll
    for (int i = 0; i < 32; i += 8)
        tile[ty + i][tx] = in[(size_t)(by + ty + i) * C + bx + tx];
    __syncthreads();
#pragma unroll
    for (int i = 0; i < 32; i += 8)
        out[(size_t)(bx + ty + i) * R + by + tx] = __float2half(tile[tx][ty + i]);
}

// ========================= Fused AKT attention (tf32 mma) =========================
#define TQ   16
#define CH   128
#define RP   516
#define QP   68
#define KPP  68
#define VPP  72
#define KVBUF (128*72)
#define ATTN_SMEM (27776*(int)sizeof(float))

__global__ __launch_bounds__(256, 2)
void attn_mma(const float* __restrict__ Q, const float* __restrict__ K,
              const float* __restrict__ V, const float* __restrict__ gammas,
              __half* __restrict__ CTX16)
{
    extern __shared__ __align__(16) float sm[];
    float* sRaw = sm;                       // 16 x 516
    float* sQ   = sm + 16 * RP;             // 16 x 68
    float* sKV  = sQ + 16 * QP;             // 2 x 128 x 72
    const uint32_t sQa  = smem_to_u32(sQ);
    const uint32_t sKVa = smem_to_u32(sKV);

    const int t    = threadIdx.x;
    const int lane = t & 31, w = t >> 5;
    const int g    = lane >> 2, tg = lane & 3;
    const int qt = blockIdx.x, h = blockIdx.y, b = blockIdx.z;
    const int i0 = qt * TQ;
    const int nch = (i0 + TQ + CH - 1) >> 7;

    // Q tile (group 0)
    {
        int r = t >> 4, c4 = t & 15;
        CP_ASYNC16(sQa + (uint32_t)(r * QP + c4 * 4) * 4u,
                   Q + (size_t)(b * SS + i0 + r) * DD + h * 64 + c4 * 4);
    }
    CP_COMMIT();
    // K chunk 0 (group 1)
    {
        const float* Kb = K + (size_t)(b * SS) * DD + h * 64;
#pragma unroll
        for (int i = 0; i < 8; i++) {
            int id = t + i * 256;
            int r = id >> 4, c4 = id & 15;
            CP_ASYNC16(sKVa + (uint32_t)(r * KPP + c4 * 4) * 4u,
                       Kb + (size_t)r * DD + c4 * 4);
        }
    }
    CP_COMMIT();

    // tail init of sRaw (cols Phase A never writes)
    {
        const int j0i = nch * CH;
        const int nf4 = (512 - j0i) >> 2;
        if (nf4 > 0) {
            for (int idx = t; idx < 16 * nf4; idx += 256) {
                int r = idx / nf4, c = idx - r * nf4;
                *(float4*)(sRaw + r * RP + j0i + c * 4) =
                    make_float4(-1e32f, -1e32f, -1e32f, -1e32f);
            }
        }
    }

    // hoist Q fragments (scale folded; 0.125 is exact pow2)
    CP_WAIT1();            // Q group done
    __syncthreads();
    uint32_t qf[8][4];
#pragma unroll
    for (int ks = 0; ks < 8; ks++) {
        const int k0 = ks * 8;
        qf[ks][0] = __float_as_uint(0.125f * sQ[(g    ) * QP + k0 + tg    ]);
        qf[ks][1] = __float_as_uint(0.125f * sQ[(g + 8) * QP + k0 + tg    ]);
        qf[ks][2] = __float_as_uint(0.125f * sQ[(g    ) * QP + k0 + tg + 4]);
        qf[ks][3] = __float_as_uint(0.125f * sQ[(g + 8) * QP + k0 + tg + 4]);
    }

    // -------- Phase A --------
    for (int c = 0; c < nch; c++) {
        CP_WAIT0();
        __syncthreads();
        if (c + 1 < nch) {
            const float* Kb = K + (size_t)(b * SS + (c + 1) * CH) * DD + h * 64;
            const uint32_t dst = sKVa + (uint32_t)(((c + 1) & 1) * KVBUF) * 4u;
#pragma unroll
            for (int i = 0; i < 8; i++) {
                int id = t + i * 256;
                int r = id >> 4, c4 = id & 15;
                CP_ASYNC16(dst + (uint32_t)(r * KPP + c4 * 4) * 4u,
                           Kb + (size_t)r * DD + c4 * 4);
            }
            CP_COMMIT();
        }
        const float* kb = sKV + (c & 1) * KVBUF;

        float acc[2][4] = {{0.f,0.f,0.f,0.f},{0.f,0.f,0.f,0.f}};
#pragma unroll
        for (int ks = 0; ks < 8; ks++) {
            const int k0 = ks * 8;
#pragma unroll
            for (int nt = 0; nt < 2; nt++) {
                const int jl = w * 16 + nt * 8 + g;
                uint32_t bf[2];
                bf[0] = __float_as_uint(kb[jl * KPP + k0 + tg    ]);
                bf[1] = __float_as_uint(kb[jl * KPP + k0 + tg + 4]);
                mma_tf32(acc[nt], qf[ks], bf);
            }
        }
        const int ilo = i0 + g, ihi = i0 + g + 8;
#pragma unroll
        for (int nt = 0; nt < 2; nt++) {
            const int j = c * CH + w * 16 + nt * 8 + 2 * tg;
            sRaw[(g    ) * RP + j    ] = (j     <= ilo) ? acc[nt][0] : -1e32f;
            sRaw[(g    ) * RP + j + 1] = (j + 1 <= ilo) ? acc[nt][1] : -1e32f;
            sRaw[(g + 8) * RP + j    ] = (j     <= ihi) ? acc[nt][2] : -1e32f;
            sRaw[(g + 8) * RP + j + 1] = (j + 1 <= ihi) ? acc[nt][3] : -1e32f;
        }
    }
    __syncthreads();   // all Phase A done before V prefetch reuses buffers

    // prefetch V chunk 0 (overlaps Phase B)
    {
        const float* Vb = V + (size_t)(b * SS) * DD + h * 64;
#pragma unroll
        for (int i = 0; i < 8; i++) {
            int id = t + i * 256;
            int r = id >> 4, c4 = id & 15;
            CP_ASYNC16(sKVa + (uint32_t)(r * VPP + c4 * 4) * 4u,
                       Vb + (size_t)r * DD + c4 * 4);
        }
    }
    CP_COMMIT();

    // -------- Phase B --------
    {
        float gm  = gammas[h];
        float sp  = (gm > 20.f) ? gm : log1pf(expf(gm));
        float gamma = -sp;
#pragma unroll
        for (int rr = 0; rr < 2; rr++) {
            const int row_i = w + rr * 8;
            const int ig = i0 + row_i;
            float* row = sRaw + row_i * RP;
            const float4* rv = (const float4*)row;

            float vals[16];
#pragma unroll
            for (int u = 0; u < 4; u++) {
                float4 v4 = rv[lane * 4 + u];
                vals[4*u+0] = v4.x; vals[4*u+1] = v4.y; vals[4*u+2] = v4.z; vals[4*u+3] = v4.w;
            }

            float mx = -1e32f;
#pragma unroll
            for (int m = 0; m < 16; m++) mx = fmaxf(mx, vals[m]);
#pragma unroll
            for (int off = 16; off > 0; off >>= 1) mx = fmaxf(mx, __shfl_xor_sync(0xffffffffu, mx, off));

            float p[16]; float s = 0.f;
#pragma unroll
            for (int m = 0; m < 16; m++) { p[m] = fexp(vals[m] - mx); s += p[m]; }
#pragma unroll
            for (int off = 16; off > 0; off >>= 1) s += __shfl_xor_sync(0xffffffffu, s, off);
            const float inv = 1.f / s;

            float local = 0.f; float cum[16];
#pragma unroll
            for (int m = 0; m < 16; m++) { local += p[m] * inv; cum[m] = local; }
            float run = local;
#pragma unroll
            for (int off = 1; off < 32; off <<= 1) {
                float vv = __shfl_up_sync(0xffffffffu, run, off);
                if (lane >= off) run += vv;
            }
            const float prefix = run - local;
            const float total  = __shfl_sync(0xffffffffu, run, 31);

#pragma unroll
            for (int m = 0; m < 16; m++) {
                int jg = lane * 16 + m;
                float suffix = fmaxf(total - (prefix + cum[m]), 0.f);
                float pe = fabsf((float)(ig - jg));
                float dist = fsqrt_ap(suffix * pe);
                float eff = fexp(dist * gamma);
                eff = fminf(fmaxf(eff, 1e-5f), 1e5f);
                vals[m] = vals[m] * eff;
            }

            float mx2 = -1e32f;
#pragma unroll
            for (int m = 0; m < 16; m++) mx2 = fmaxf(mx2, vals[m]);
#pragma unroll
            for (int off = 16; off > 0; off >>= 1) mx2 = fmaxf(mx2, __shfl_xor_sync(0xffffffffu, mx2, off));
            float s2 = 0.f;
#pragma unroll
            for (int m = 0; m < 16; m++) { vals[m] = fexp(vals[m] - mx2); s2 += vals[m]; }
#pragma unroll
            for (int off = 16; off > 0; off >>= 1) s2 += __shfl_xor_sync(0xffffffffu, s2, off);
            const float inv2 = 1.f / s2;

            float4* wv = (float4*)row;
#pragma unroll
            for (int u = 0; u < 4; u++) {
                float4 o;
                o.x = vals[4*u+0] * inv2; o.y = vals[4*u+1] * inv2;
                o.z = vals[4*u+2] * inv2; o.w = vals[4*u+3] * inv2;
                wv[lane * 4 + u] = o;
            }
        }
    }
    __syncthreads();

    // -------- Phase C --------
    float oc[4] = {0.f, 0.f, 0.f, 0.f};
    for (int c = 0; c < nch; c++) {
        CP_WAIT0();
        __syncthreads();
        if (c + 1 < nch) {
            const float* Vb = V + (size_t)(b * SS + (c + 1) * CH) * DD + h * 64;
            const uint32_t dst = sKVa + (uint32_t)(((c + 1) & 1) * KVBUF) * 4u;
#pragma unroll
            for (int i = 0; i < 8; i++) {
                int id = t + i * 256;
                int r = id >> 4, c4 = id & 15;
                CP_ASYNC16(dst + (uint32_t)(r * VPP + c4 * 4) * 4u,
                           Vb + (size_t)r * DD + c4 * 4);
            }
            CP_COMMIT();
        }
        const float* vb = sKV + (c & 1) * KVBUF;

#pragma unroll
        for (int k0 = 0; k0 < CH; k0 += 8) {
            const int jcol = c * CH + k0 + tg;
            uint32_t af[4];
            af[0] = __float_as_uint(sRaw[(g    ) * RP + jcol    ]);
            af[1] = __float_as_uint(sRaw[(g + 8) * RP + jcol    ]);
            af[2] = __float_as_uint(sRaw[(g    ) * RP + jcol + 4]);
            af[3] = __float_as_uint(sRaw[(g + 8) * RP + jcol + 4]);
            uint32_t bf[2];
            bf[0] = __float_as_uint(vb[(k0 + tg    ) * VPP + w * 8 + g]);
            bf[1] = __float_as_uint(vb[(k0 + tg + 4) * VPP + w * 8 + g]);
            mma_tf32(oc, af, bf);
        }
    }

    const int col = h * 64 + w * 8 + 2 * tg;
    *(__half2*)(CTX16 + (size_t)(b * SS + i0 + g    ) * DD + col) = __floats2half2_rn(oc[0], oc[1]);
    *(__half2*)(CTX16 + (size_t)(b * SS + i0 + g + 8) * DD + col) = __floats2half2_rn(oc[2], oc[3]);
}

// ---------------- residual add + LayerNorm (optional fp16 side copy) ----------------
__global__ __launch_bounds__(256)
void add_ln(const float* __restrict__ A, const float* __restrict__ B,
            const float* __restrict__ g, const float* __restrict__ be,
            float* __restrict__ O, __half* __restrict__ O16)
{
    const int row = blockIdx.x;
    const int t = threadIdx.x;
    const float* a = A + (size_t)row * DD;
    const float* b = B + (size_t)row * DD;

    float x0 = a[t] + b[t];
    float x1 = a[t + 256] + b[t + 256];
    float s  = x0 + x1;
    float sq = x0 * x0 + x1 * x1;

    __shared__ float rs[8], rq[8];
    __shared__ float sMu, sRstd;
    const int lane = t & 31, w = t >> 5;
#pragma unroll
    for (int off = 16; off > 0; off >>= 1) {
        s  += __shfl_xor_sync(0xffffffffu, s, off);
        sq += __shfl_xor_sync(0xffffffffu, sq, off);
    }
    if (lane == 0) { rs[w] = s; rq[w] = sq; }
    __syncthreads();
    if (t == 0) {
        float S = 0.f, SQ = 0.f;
#pragma unroll
        for (int i = 0; i < 8; i++) { S += rs[i]; SQ += rq[i]; }
        float mu = S * (1.f / 512.f);
        float var = fmaxf(SQ * (1.f / 512.f) - mu * mu, 0.f);
        sMu = mu;
        sRstd = rsqrtf(var + 1e-5f);
    }
    __syncthreads();
    const float mu = sMu, rstd = sRstd;
    float y0 = (x0 - mu) * rstd * g[t]       + be[t];
    float y1 = (x1 - mu) * rstd * g[t + 256] + be[t + 256];
    O[(size_t)row * DD + t]       = y0;
    O[(size_t)row * DD + t + 256] = y1;
    if (O16) {
        O16[(size_t)row * DD + t]       = __float2half(y0);
        O16[(size_t)row * DD + t + 256] = __float2half(y1);
    }
}

// ---------------- launch ----------------
extern "C" void kernel_launch(void* const* d_in, const int* in_sizes, int n_in,
                              void* d_out, int out_size)
{
    const float* query  = (const float*)d_in[0];
    const float* key    = (const float*)d_in[1];
    const float* values = (const float*)d_in[2];
    const float* Wk     = (const float*)d_in[3];
    const float* bk     = (const float*)d_in[4];
    const float* Wv     = (const float*)d_in[5];
    const float* bv     = (const float*)d_in[6];
    const float* Wo     = (const float*)d_in[7];
    const float* bo     = (const float*)d_in[8];
    const float* gammas = (const float*)d_in[9];
    const float* ln1_g  = (const float*)d_in[10];
    const float* ln1_b  = (const float*)d_in[11];
    const float* W1     = (const float*)d_in[12];
    const float* b1     = (const float*)d_in[13];
    const float* W2     = (const float*)d_in[14];
    const float* b2     = (const float*)d_in[15];
    const float* ln2_g  = (const float*)d_in[16];
    const float* ln2_b  = (const float*)d_in[17];
    float* out = (float*)d_out;

    float *q, *k, *v, *ao, *x1, *f2;
    __half *in16q, *in16k, *in16v, *ctx16, *x116, *h116;
    __half *wkT16, *wvT16, *woT16, *w1T16, *w2T16;
    cudaGetSymbolAddress((void**)&q,   g_q);
    cudaGetSymbolAddress((void**)&k,   g_k);
    cudaGetSymbolAddress((void**)&v,   g_v);
    cudaGetSymbolAddress((void**)&ao,  g_ao);
    cudaGetSymbolAddress((void**)&x1,  g_x1);
    cudaGetSymbolAddress((void**)&f2,  g_f2);
    cudaGetSymbolAddress((void**)&in16q, g_in16q);
    cudaGetSymbolAddress((void**)&in16k, g_in16k);
    cudaGetSymbolAddress((void**)&in16v, g_in16v);
    cudaGetSymbolAddress((void**)&ctx16, g_ctx16);
    cudaGetSymbolAddress((void**)&x116,  g_x116);
    cudaGetSymbolAddress((void**)&h116,  g_h116);
    cudaGetSymbolAddress((void**)&wkT16, g_wkT16);
    cudaGetSymbolAddress((void**)&wvT16, g_wvT16);
    cudaGetSymbolAddress((void**)&woT16, g_woT16);
    cudaGetSymbolAddress((void**)&w1T16, g_w1T16);
    cudaGetSymbolAddress((void**)&w2T16, g_w2T16);

    cudaFuncSetAttribute(attn_mma, cudaFuncAttributeMaxDynamicSharedMemorySize, ATTN_SMEM);
    cudaFuncSetAttribute(gemm_h<false,false>, cudaFuncAttributeMaxDynamicSharedMemorySize, GEMM_H_SMEM);
    cudaFuncSetAttribute(gemm_h<true, true >, cudaFuncAttributeMaxDynamicSharedMemorySize, GEMM_H_SMEM);
    cudaFuncSetAttribute(gemm_proj3_h, cudaFuncAttributeMaxDynamicSharedMemorySize, GEMM_H_SMEM);

    // ---- prep: fp16 conversions + weight transposes ----
    conv_fp16_3<<<dim3(512, 1, 3), 256>>>(query, key, values, in16q, in16k, in16v);
    transpose_h<<<dim3(16, 16), 256>>>(Wk, wkT16, DD, DD);
    transpose_h<<<dim3(16, 16), 256>>>(Wv, wvT16, DD, DD);
    transpose_h<<<dim3(16, 16), 256>>>(Wo, woT16, DD, DD);
    transpose_h<<<dim3(64, 16), 256>>>(W1, w1T16, DD, DFFN);
    transpose_h<<<dim3(16, 64), 256>>>(W2, w2T16, DFFN, DD);

    const dim3 gProj (DD / 128,   MROWS / 128);     // (4, 64)
    const dim3 gProj3(DD / 128,   MROWS / 128, 3);
    const dim3 gFF1  (DFFN / 128, MROWS / 128);     // (16, 64)

    // projections
    gemm_proj3_h<<<gProj3, 256, GEMM_H_SMEM>>>(in16q, in16k, in16v, wkT16, wvT16,
                                               bk, bv, q, k, v);

    attn_mma<<<dim3(SS / TQ, HH, BB), 256, ATTN_SMEM>>>(q, k, v, gammas, ctx16);

    gemm_h<false,false><<<gProj, 256, GEMM_H_SMEM>>>(ctx16, woT16, bo, ao, (__half*)0,
                                                     MROWS, DD, DD);

    add_ln<<<MROWS, 256>>>(query, ao, ln1_g, ln1_b, x1, x116);

    gemm_h<true, true ><<<gFF1, 256, GEMM_H_SMEM>>>(x116, w1T16, b1, (float*)0, h116,
                                                    MROWS, DFFN, DD);
    gemm_h<false,false><<<gProj, 256, GEMM_H_SMEM>>>(h116, w2T16, b2, f2, (__half*)0,
                                                     MROWS, DD, DFFN);

    add_ln<<<MROWS, 256>>>(x1, f2, ln2_g, ln2_b, out, (__half*)0);
}

// round 8
// speedup vs baseline: 5.6843x; 1.1170x over previous
#include <cuda_runtime.h>
#include <cuda_fp16.h>
#include <cstdint>
#include <math.h>

// Problem constants
#define BB   16
#define SS   512
#define DD   512
#define HH   8
#define DK   64
#define DFFN 2048
#define MROWS (BB*SS)   // 8192

// ---------------- scratch (static device globals; no allocation) ----------------
__device__ float g_ao [MROWS*DD];
__device__ float g_x1 [MROWS*DD];
__device__ float g_f2 [MROWS*DD];
// fp16 activations
__device__ __half g_in16q[MROWS*DD];
__device__ __half g_in16k[MROWS*DD];
__device__ __half g_in16v[MROWS*DD];
__device__ __half g_qh  [MROWS*DD];
__device__ __half g_kh  [MROWS*DD];
__device__ __half g_vh  [MROWS*DD];
__device__ __half g_ctx16[MROWS*DD];
__device__ __half g_x116 [MROWS*DD];
__device__ __half g_h116 [MROWS*DFFN];
// fp16 transposed weights [N][K]
__device__ __half g_wkT16[DD*DD];
__device__ __half g_wvT16[DD*DD];
__device__ __half g_woT16[DD*DD];
__device__ __half g_w1T16[DFFN*DD];
__device__ __half g_w2T16[DD*DFFN];

// ---------------- helpers ----------------
__device__ __forceinline__ uint32_t smem_to_u32(const void* p) {
    uint32_t a;
    asm("{ .reg .u64 tmp; cvta.to.shared.u64 tmp, %1; cvt.u32.u64 %0, tmp; }" : "=r"(a) : "l"(p));
    return a;
}
#define CP_ASYNC16(saddr, gptr) \
    asm volatile("cp.async.cg.shared.global [%0], [%1], 16;" :: "r"(saddr), "l"(gptr))
#define CP_COMMIT() asm volatile("cp.async.commit_group;" ::: "memory")
#define CP_WAIT0()  asm volatile("cp.async.wait_group 0;" ::: "memory")
#define CP_WAIT1()  asm volatile("cp.async.wait_group 1;" ::: "memory")

// mma m16n8k16 fp16, fp32 accumulate
__device__ __forceinline__ void mma_f16(float* c, const uint32_t* a, const uint32_t* b) {
    asm volatile(
        "mma.sync.aligned.m16n8k16.row.col.f32.f16.f16.f32 "
        "{%0,%1,%2,%3}, {%4,%5,%6,%7}, {%8,%9}, {%0,%1,%2,%3};"
        : "+f"(c[0]), "+f"(c[1]), "+f"(c[2]), "+f"(c[3])
        : "r"(a[0]), "r"(a[1]), "r"(a[2]), "r"(a[3]), "r"(b[0]), "r"(b[1]));
}
// transposed 8x8 b16 matrix pair load (B operand for m16n8k16)
__device__ __forceinline__ void ldmatrix_x2_trans(uint32_t& r0, uint32_t& r1, uint32_t addr) {
    asm volatile("ldmatrix.sync.aligned.m8n8.x2.trans.shared.b16 {%0,%1}, [%2];"
                 : "=r"(r0), "=r"(r1) : "r"(addr));
}

__device__ __forceinline__ float fexp(float x) {
    float y;
    asm("ex2.approx.f32 %0, %1;" : "=f"(y) : "f"(x * 1.4426950408889634f));
    return y;
}
__device__ __forceinline__ float fsqrt_ap(float x) {
    float y;
    asm("sqrt.approx.f32 %0, %1;" : "=f"(y) : "f"(x));
    return y;
}

// ========================= fp16 mma GEMM =========================
#define HP 72
#define TILE_H (128*HP)
#define STAGE_H (2*TILE_H)
#define GEMM_H_SMEM (2*STAGE_H*(int)sizeof(__half))

__device__ __forceinline__ void fill_h(const __half* __restrict__ A,
                                       const __half* __restrict__ Bt,
                                       int K, int bm, int bn, int kc,
                                       uint32_t sA, uint32_t sB, int t)
{
#pragma unroll
    for (int i = 0; i < 4; i++) {
        int id = t + i * 256;
        int row = id >> 3, c = id & 7;
        CP_ASYNC16(sA + (uint32_t)(row * HP + c * 8) * 2u,
                   A + (size_t)(bm + row) * K + kc * 64 + c * 8);
    }
#pragma unroll
    for (int i = 0; i < 4; i++) {
        int id = t + i * 256;
        int row = id >> 3, c = id & 7;
        CP_ASYNC16(sB + (uint32_t)(row * HP + c * 8) * 2u,
                   Bt + (size_t)(bn + row) * K + kc * 64 + c * 8);
    }
}

template<bool RELU, bool OUT16>
__device__ __forceinline__ void gemm_h_body(const __half* __restrict__ A,
                                            const __half* __restrict__ Bt,
                                            const float* __restrict__ bias,
                                            float* __restrict__ C,
                                            __half* __restrict__ C16,
                                            int N, int K, int bm, int bn,
                                            __half* smem_h)
{
    const int t    = threadIdx.x;
    const int lane = t & 31, wid = t >> 5;
    const int g    = lane >> 2, tg = lane & 3;
    const int wm   = (wid >> 2) * 64;
    const int wn   = (wid & 3) * 32;
    const uint32_t sbase = smem_to_u32(smem_h);

    float acc[4][4][4];
#pragma unroll
    for (int mt = 0; mt < 4; mt++)
#pragma unroll
        for (int nt = 0; nt < 4; nt++)
#pragma unroll
            for (int r = 0; r < 4; r++) acc[mt][nt][r] = 0.f;

    const int nk = K >> 6;

    fill_h(A, Bt, K, bm, bn, 0, sbase, sbase + TILE_H * 2, t);
    CP_COMMIT();

    for (int kc = 0; kc < nk; kc++) {
        CP_WAIT0();
        __syncthreads();
        if (kc + 1 < nk) {
            const uint32_t off = ((kc + 1) & 1) * (uint32_t)(STAGE_H * 2);
            fill_h(A, Bt, K, bm, bn, kc + 1, sbase + off, sbase + off + TILE_H * 2, t);
            CP_COMMIT();
        }
        const __half* aS = smem_h + (kc & 1) * STAGE_H;
        const __half* bS = aS + TILE_H;

#pragma unroll
        for (int ks = 0; ks < 4; ks++) {
            const int k0 = ks * 16;
            uint32_t af[4][4];
#pragma unroll
            for (int mt = 0; mt < 4; mt++) {
                const int mrow = wm + mt * 16 + g;
                af[mt][0] = *(const uint32_t*)(aS + mrow * HP + k0 + 2 * tg);
                af[mt][1] = *(const uint32_t*)(aS + (mrow + 8) * HP + k0 + 2 * tg);
                af[mt][2] = *(const uint32_t*)(aS + mrow * HP + k0 + 2 * tg + 8);
                af[mt][3] = *(const uint32_t*)(aS + (mrow + 8) * HP + k0 + 2 * tg + 8);
            }
            uint32_t bf[4][2];
#pragma unroll
            for (int nt = 0; nt < 4; nt++) {
                const int ncol = wn + nt * 8 + g;
                bf[nt][0] = *(const uint32_t*)(bS + ncol * HP + k0 + 2 * tg);
                bf[nt][1] = *(const uint32_t*)(bS + ncol * HP + k0 + 2 * tg + 8);
            }
#pragma unroll
            for (int mt = 0; mt < 4; mt++)
#pragma unroll
                for (int nt = 0; nt < 4; nt++)
                    mma_f16(acc[mt][nt], af[mt], bf[nt]);
        }
    }

#pragma unroll
    for (int mt = 0; mt < 4; mt++) {
#pragma unroll
        for (int nt = 0; nt < 4; nt++) {
            const int row0 = bm + wm + mt * 16 + g;
            const int col  = bn + wn + nt * 8 + 2 * tg;
            float b0 = bias[col], b1 = bias[col + 1];
            float v0 = acc[mt][nt][0] + b0, v1 = acc[mt][nt][1] + b1;
            float v2 = acc[mt][nt][2] + b0, v3 = acc[mt][nt][3] + b1;
            if (RELU) {
                v0 = fmaxf(v0, 0.f); v1 = fmaxf(v1, 0.f);
                v2 = fmaxf(v2, 0.f); v3 = fmaxf(v3, 0.f);
            }
            if (OUT16) {
                *(__half2*)(C16 + (size_t)row0 * N + col)       = __floats2half2_rn(v0, v1);
                *(__half2*)(C16 + (size_t)(row0 + 8) * N + col) = __floats2half2_rn(v2, v3);
            } else {
                *(float2*)(C + (size_t)row0 * N + col)       = make_float2(v0, v1);
                *(float2*)(C + (size_t)(row0 + 8) * N + col) = make_float2(v2, v3);
            }
        }
    }
}

template<bool RELU, bool OUT16>
__global__ __launch_bounds__(256, 2)
void gemm_h(const __half* __restrict__ A, const __half* __restrict__ Bt,
            const float* __restrict__ bias, float* __restrict__ C,
            __half* __restrict__ C16, int M, int N, int K)
{
    extern __shared__ __align__(16) __half smem_h[];
    gemm_h_body<RELU, OUT16>(A, Bt, bias, C, C16, N, K,
                             blockIdx.y * 128, blockIdx.x * 128, smem_h);
}

// batched q/k/v projections (fp16 in, fp16 out); q,k share Wk/bk
__global__ __launch_bounds__(256, 2)
void gemm_proj3_h(const __half* __restrict__ A0, const __half* __restrict__ A1,
                  const __half* __restrict__ A2,
                  const __half* __restrict__ WkT, const __half* __restrict__ WvT,
                  const float* __restrict__ bk, const float* __restrict__ bv,
                  __half* __restrict__ C0, __half* __restrict__ C1, __half* __restrict__ C2)
{
    extern __shared__ __align__(16) __half smem_h[];
    const int z = blockIdx.z;
    const __half* A = (z == 0) ? A0 : (z == 1) ? A1 : A2;
    const __half* W = (z == 2) ? WvT : WkT;
    const float* bias = (z == 2) ? bv : bk;
    __half* C16 = (z == 0) ? C0 : (z == 1) ? C1 : C2;
    gemm_h_body<false, true>(A, W, bias, ((float*)0), C16, DD, DD,
                             blockIdx.y * 128, blockIdx.x * 128, smem_h);
}

// ---------------- prep kernels ----------------
__global__ __launch_bounds__(256)
void conv_fp16_3(const float* __restrict__ s0, const float* __restrict__ s1,
                 const float* __restrict__ s2,
                 __half* __restrict__ d0, __half* __restrict__ d1, __half* __restrict__ d2)
{
    const int z = blockIdx.z;
    const float* s = (z == 0) ? s0 : (z == 1) ? s1 : s2;
    __half* d = (z == 0) ? d0 : (z == 1) ? d1 : d2;
    const int n4 = MROWS * DD / 4;
    for (int i = blockIdx.x * 256 + threadIdx.x; i < n4; i += gridDim.x * 256) {
        float4 v = ((const float4*)s)[i];
        ((__half2*)d)[2 * i    ] = __floats2half2_rn(v.x, v.y);
        ((__half2*)d)[2 * i + 1] = __floats2half2_rn(v.z, v.w);
    }
}

// all 5 weight transposes in one launch (z selects matrix; early-exit out of range)
__global__ __launch_bounds__(256)
void transpose_h_all(const float* __restrict__ Wk, const float* __restrict__ Wv,
                     const float* __restrict__ Wo, const float* __restrict__ W1,
                     const float* __restrict__ W2,
                     __half* __restrict__ o0, __half* __restrict__ o1,
                     __half* __restrict__ o2, __half* __restrict__ o3,
                     __half* __restrict__ o4)
{
    const int z = blockIdx.z;
    const float* in; __half* out; int R, C;
    switch (z) {
        case 0: in = Wk; out = o0; R = DD;   C = DD;   break;
        case 1: in = Wv; out = o1; R = DD;   C = DD;   break;
        case 2: in = Wo; out = o2; R = DD;   C = DD;   break;
        case 3: in = W1; out = o3; R = DD;   C = DFFN; break;
        default:in = W2; out = o4; R = DFFN; C = DD;   break;
    }
    const int bx = blockIdx.x * 32;
    const int by = blockIdx.y * 32;
    if (bx >= C || by >= R) return;
    __shared__ float tile[32][33];
    const int tx = threadIdx.x & 31;
    const int ty = threadIdx.x >> 5;
#pragma unroll
    for (int i = 0; i < 32; i += 8)
        tile[ty + i][tx] = in[(size_t)(by + ty + i) * C + bx + tx];
    __syncthreads();
#pragma unroll
    for (int i = 0; i < 32; i += 8)
        out[(size_t)(bx + ty + i) * R + by + tx] = __float2half(tile[tx][ty + i]);
}

// ========================= Fused AKT attention (fp16 mma) =========================
// Block = (qt, h, b), 256 threads. fp16 Q/K/V, fp32 score buffer, fp16 prob buffer.
#define TQ   16
#define CH   128
#define RP   516            // fp32 score pitch (floats)
#define PP   520            // fp16 prob pitch (halves)
#define QP   72             // fp16 Q pitch (halves)
#define KVP  72             // fp16 K/V pitch (halves)
#define KVBUF (128*KVP)     // halves per buffer
// bytes: sRaw 16*516*4=33024 | sP 16*520*2=16640 | sQ 16*72*2=2304 | sKV 2*128*72*2=36864
#define OFF_P   33024
#define OFF_Q   (33024+16640)
#define OFF_KV  (33024+16640+2304)
#define ATTN_SMEM (33024+16640+2304+36864)

__global__ __launch_bounds__(256, 2)
void attn_mma(const __half* __restrict__ Q, const __half* __restrict__ K,
              const __half* __restrict__ V, const float* __restrict__ gammas,
              __half* __restrict__ CTX16)
{
    extern __shared__ __align__(16) char smem_c[];
    float*  sRaw = (float*)smem_c;
    __half* sP   = (__half*)(smem_c + OFF_P);
    __half* sQ   = (__half*)(smem_c + OFF_Q);
    __half* sKV  = (__half*)(smem_c + OFF_KV);
    const uint32_t sQa  = smem_to_u32(sQ);
    const uint32_t sKVa = smem_to_u32(sKV);

    const int t    = threadIdx.x;
    const int lane = t & 31, w = t >> 5;
    const int g    = lane >> 2, tg = lane & 3;
    const int qt = blockIdx.x, h = blockIdx.y, b = blockIdx.z;
    const int i0 = qt * TQ;
    const int nch = (i0 + TQ + CH - 1) >> 7;

    // Q tile 16x64 fp16 (group 0): 128 cp.asyncs
    if (t < 128) {
        int r = t >> 3, c8 = t & 7;
        CP_ASYNC16(sQa + (uint32_t)(r * QP + c8 * 8) * 2u,
                   Q + (size_t)(b * SS + i0 + r) * DD + h * 64 + c8 * 8);
    }
    CP_COMMIT();
    // K chunk 0 (group 1)
    {
        const __half* Kb = K + (size_t)(b * SS) * DD + h * 64;
#pragma unroll
        for (int i = 0; i < 4; i++) {
            int id = t + i * 256;
            int r = id >> 3, c8 = id & 7;
            CP_ASYNC16(sKVa + (uint32_t)(r * KVP + c8 * 8) * 2u,
                       Kb + (size_t)r * DD + c8 * 8);
        }
    }
    CP_COMMIT();

    // tail init of sRaw (cols Phase A never writes)
    {
        const int j0i = nch * CH;
        const int nf4 = (512 - j0i) >> 2;
        if (nf4 > 0) {
            for (int idx = t; idx < 16 * nf4; idx += 256) {
                int r = idx / nf4, c = idx - r * nf4;
                *(float4*)(sRaw + r * RP + j0i + c * 4) =
                    make_float4(-1e32f, -1e32f, -1e32f, -1e32f);
            }
        }
    }

    // hoist Q fragments (fp16, 4 k-steps of 16)
    CP_WAIT1();
    __syncthreads();
    uint32_t qf[4][4];
#pragma unroll
    for (int ks = 0; ks < 4; ks++) {
        const int k0 = ks * 16;
        qf[ks][0] = *(const uint32_t*)(sQ + (g    ) * QP + k0 + 2 * tg);
        qf[ks][1] = *(const uint32_t*)(sQ + (g + 8) * QP + k0 + 2 * tg);
        qf[ks][2] = *(const uint32_t*)(sQ + (g    ) * QP + k0 + 2 * tg + 8);
        qf[ks][3] = *(const uint32_t*)(sQ + (g + 8) * QP + k0 + 2 * tg + 8);
    }

    // -------- Phase A: raw scores (unscaled) --------
    for (int c = 0; c < nch; c++) {
        CP_WAIT0();
        __syncthreads();
        if (c + 1 < nch) {
            const __half* Kb = K + (size_t)(b * SS + (c + 1) * CH) * DD + h * 64;
            const uint32_t dst = sKVa + (uint32_t)(((c + 1) & 1) * KVBUF) * 2u;
#pragma unroll
            for (int i = 0; i < 4; i++) {
                int id = t + i * 256;
                int r = id >> 3, c8 = id & 7;
                CP_ASYNC16(dst + (uint32_t)(r * KVP + c8 * 8) * 2u,
                           Kb + (size_t)r * DD + c8 * 8);
            }
            CP_COMMIT();
        }
        const __half* kb = sKV + (c & 1) * KVBUF;

        float acc[2][4] = {{0.f,0.f,0.f,0.f},{0.f,0.f,0.f,0.f}};
#pragma unroll
        for (int ks = 0; ks < 4; ks++) {
            const int k0 = ks * 16;
#pragma unroll
            for (int nt = 0; nt < 2; nt++) {
                const int jl = w * 16 + nt * 8 + g;
                uint32_t bf[2];
                bf[0] = *(const uint32_t*)(kb + jl * KVP + k0 + 2 * tg);
                bf[1] = *(const uint32_t*)(kb + jl * KVP + k0 + 2 * tg + 8);
                mma_f16(acc[nt], qf[ks], bf);
            }
        }
        const int ilo = i0 + g, ihi = i0 + g + 8;
#pragma unroll
        for (int nt = 0; nt < 2; nt++) {
            const int j = c * CH + w * 16 + nt * 8 + 2 * tg;
            sRaw[(g    ) * RP + j    ] = (j     <= ilo) ? acc[nt][0] : -1e32f;
            sRaw[(g    ) * RP + j + 1] = (j + 1 <= ilo) ? acc[nt][1] : -1e32f;
            sRaw[(g + 8) * RP + j    ] = (j     <= ihi) ? acc[nt][2] : -1e32f;
            sRaw[(g + 8) * RP + j + 1] = (j + 1 <= ihi) ? acc[nt][3] : -1e32f;
        }
    }
    __syncthreads();

    // prefetch V chunk 0 (overlaps Phase B)
    {
        const __half* Vb = V + (size_t)(b * SS) * DD + h * 64;
#pragma unroll
        for (int i = 0; i < 4; i++) {
            int id = t + i * 256;
            int r = id >> 3, c8 = id & 7;
            CP_ASYNC16(sKVa + (uint32_t)(r * KVP + c8 * 8) * 2u,
                       Vb + (size_t)r * DD + c8 * 8);
        }
    }
    CP_COMMIT();

    // -------- Phase B: softmax -> cumsum -> decay -> softmax; write fp16 probs --------
    {
        float gm  = gammas[h];
        float sp  = (gm > 20.f) ? gm : log1pf(expf(gm));
        float gamma = -sp;
#pragma unroll
        for (int rr = 0; rr < 2; rr++) {
            const int row_i = w + rr * 8;
            const int ig = i0 + row_i;
            const float4* rv = (const float4*)(sRaw + row_i * RP);

            float vals[16];
#pragma unroll
            for (int u = 0; u < 4; u++) {
                float4 v4 = rv[lane * 4 + u];
                vals[4*u+0] = 0.125f * v4.x; vals[4*u+1] = 0.125f * v4.y;
                vals[4*u+2] = 0.125f * v4.z; vals[4*u+3] = 0.125f * v4.w;
            }

            float mx = -1e32f;
#pragma unroll
            for (int m = 0; m < 16; m++) mx = fmaxf(mx, vals[m]);
#pragma unroll
            for (int off = 16; off > 0; off >>= 1) mx = fmaxf(mx, __shfl_xor_sync(0xffffffffu, mx, off));

            float p[16]; float s = 0.f;
#pragma unroll
            for (int m = 0; m < 16; m++) { p[m] = fexp(vals[m] - mx); s += p[m]; }
#pragma unroll
            for (int off = 16; off > 0; off >>= 1) s += __shfl_xor_sync(0xffffffffu, s, off);
            const float inv = 1.f / s;

            float local = 0.f; float cum[16];
#pragma unroll
            for (int m = 0; m < 16; m++) { local += p[m] * inv; cum[m] = local; }
            float run = local;
#pragma unroll
            for (int off = 1; off < 32; off <<= 1) {
                float vv = __shfl_up_sync(0xffffffffu, run, off);
                if (lane >= off) run += vv;
            }
            const float prefix = run - local;
            const float total  = __shfl_sync(0xffffffffu, run, 31);

#pragma unroll
            for (int m = 0; m < 16; m++) {
                int jg = lane * 16 + m;
                float suffix = fmaxf(total - (prefix + cum[m]), 0.f);
                float pe = fabsf((float)(ig - jg));
                float dist = fsqrt_ap(suffix * pe);
                float eff = fexp(dist * gamma);
                eff = fminf(fmaxf(eff, 1e-5f), 1e5f);
                vals[m] = vals[m] * eff;
            }

            float mx2 = -1e32f;
#pragma unroll
            for (int m = 0; m < 16; m++) mx2 = fmaxf(mx2, vals[m]);
#pragma unroll
            for (int off = 16; off > 0; off >>= 1) mx2 = fmaxf(mx2, __shfl_xor_sync(0xffffffffu, mx2, off));
            float s2 = 0.f;
#pragma unroll
            for (int m = 0; m < 16; m++) { vals[m] = fexp(vals[m] - mx2); s2 += vals[m]; }
#pragma unroll
            for (int off = 16; off > 0; off >>= 1) s2 += __shfl_xor_sync(0xffffffffu, s2, off);
            const float inv2 = 1.f / s2;

            __half2* wp = (__half2*)(sP + row_i * PP + lane * 16);
#pragma unroll
            for (int u = 0; u < 8; u++)
                wp[u] = __floats2half2_rn(vals[2*u] * inv2, vals[2*u+1] * inv2);
        }
    }
    __syncthreads();

    // -------- Phase C: O = P V via fp16 mma (ldmatrix.trans for V) --------
    float oc[4] = {0.f, 0.f, 0.f, 0.f};
    const int lrow = lane & 15;     // ldmatrix row provider index
    for (int c = 0; c < nch; c++) {
        CP_WAIT0();
        __syncthreads();
        if (c + 1 < nch) {
            const __half* Vb = V + (size_t)(b * SS + (c + 1) * CH) * DD + h * 64;
            const uint32_t dst = sKVa + (uint32_t)(((c + 1) & 1) * KVBUF) * 2u;
#pragma unroll
            for (int i = 0; i < 4; i++) {
                int id = t + i * 256;
                int r = id >> 3, c8 = id & 7;
                CP_ASYNC16(dst + (uint32_t)(r * KVP + c8 * 8) * 2u,
                           Vb + (size_t)r * DD + c8 * 8);
            }
            CP_COMMIT();
        }
        const uint32_t vba = sKVa + (uint32_t)((c & 1) * KVBUF) * 2u;

#pragma unroll
        for (int k0 = 0; k0 < CH; k0 += 16) {
            const int jcol = c * CH + k0;
            uint32_t af[4];
            af[0] = *(const uint32_t*)(sP + (g    ) * PP + jcol + 2 * tg);
            af[1] = *(const uint32_t*)(sP + (g + 8) * PP + jcol + 2 * tg);
            af[2] = *(const uint32_t*)(sP + (g    ) * PP + jcol + 2 * tg + 8);
            af[3] = *(const uint32_t*)(sP + (g + 8) * PP + jcol + 2 * tg + 8);
            uint32_t bf[2];
            ldmatrix_x2_trans(bf[0], bf[1],
                              vba + (uint32_t)((k0 + lrow) * KVP + w * 8) * 2u);
            mma_f16(oc, af, bf);
        }
    }

    const int col = h * 64 + w * 8 + 2 * tg;
    *(__half2*)(CTX16 + (size_t)(b * SS + i0 + g    ) * DD + col) = __floats2half2_rn(oc[0], oc[1]);
    *(__half2*)(CTX16 + (size_t)(b * SS + i0 + g + 8) * DD + col) = __floats2half2_rn(oc[2], oc[3]);
}

// ---------------- residual add + LayerNorm (optional fp16 side copy) ----------------
__global__ __launch_bounds__(256)
void add_ln(const float* __restrict__ A, const float* __restrict__ B,
            const float* __restrict__ g, const float* __restrict__ be,
            float* __restrict__ O, __half* __restrict__ O16)
{
    const int row = blockIdx.x;
    const int t = threadIdx.x;
    const float* a = A + (size_t)row * DD;
    const float* b = B + (size_t)row * DD;

    float x0 = a[t] + b[t];
    float x1 = a[t + 256] + b[t + 256];
    float s  = x0 + x1;
    float sq = x0 * x0 + x1 * x1;

    __shared__ float rs[8], rq[8];
    __shared__ float sMu, sRstd;
    const int lane = t & 31, w = t >> 5;
#pragma unroll
    for (int off = 16; off > 0; off >>= 1) {
        s  += __shfl_xor_sync(0xffffffffu, s, off);
        sq += __shfl_xor_sync(0xffffffffu, sq, off);
    }
    if (lane == 0) { rs[w] = s; rq[w] = sq; }
    __syncthreads();
    if (t == 0) {
        float S = 0.f, SQ = 0.f;
#pragma unroll
        for (int i = 0; i < 8; i++) { S += rs[i]; SQ += rq[i]; }
        float mu = S * (1.f / 512.f);
        float var = fmaxf(SQ * (1.f / 512.f) - mu * mu, 0.f);
        sMu = mu;
        sRstd = rsqrtf(var + 1e-5f);
    }
    __syncthreads();
    const float mu = sMu, rstd = sRstd;
    float y0 = (x0 - mu) * rstd * g[t]       + be[t];
    float y1 = (x1 - mu) * rstd * g[t + 256] + be[t + 256];
    O[(size_t)row * DD + t]       = y0;
    O[(size_t)row * DD + t + 256] = y1;
    if (O16) {
        O16[(size_t)row * DD + t]       = __float2half(y0);
        O16[(size_t)row * DD + t + 256] = __float2half(y1);
    }
}

// ---------------- launch ----------------
extern "C" void kernel_launch(void* const* d_in, const int* in_sizes, int n_in,
                              void* d_out, int out_size)
{
    const float* query  = (const float*)d_in[0];
    const float* key    = (const float*)d_in[1];
    const float* values = (const float*)d_in[2];
    const float* Wk     = (const float*)d_in[3];
    const float* bk     = (const float*)d_in[4];
    const float* Wv     = (const float*)d_in[5];
    const float* bv     = (const float*)d_in[6];
    const float* Wo     = (const float*)d_in[7];
    const float* bo     = (const float*)d_in[8];
    const float* gammas = (const float*)d_in[9];
    const float* ln1_g  = (const float*)d_in[10];
    const float* ln1_b  = (const float*)d_in[11];
    const float* W1     = (const float*)d_in[12];
    const float* b1     = (const float*)d_in[13];
    const float* W2     = (const float*)d_in[14];
    const float* b2     = (const float*)d_in[15];
    const float* ln2_g  = (const float*)d_in[16];
    const float* ln2_b  = (const float*)d_in[17];
    float* out = (float*)d_out;

    float *ao, *x1, *f2;
    __half *in16q, *in16k, *in16v, *qh, *kh, *vh, *ctx16, *x116, *h116;
    __half *wkT16, *wvT16, *woT16, *w1T16, *w2T16;
    cudaGetSymbolAddress((void**)&ao,  g_ao);
    cudaGetSymbolAddress((void**)&x1,  g_x1);
    cudaGetSymbolAddress((void**)&f2,  g_f2);
    cudaGetSymbolAddress((void**)&in16q, g_in16q);
    cudaGetSymbolAddress((void**)&in16k, g_in16k);
    cudaGetSymbolAddress((void**)&in16v, g_in16v);
    cudaGetSymbolAddress((void**)&qh,  g_qh);
    cudaGetSymbolAddress((void**)&kh,  g_kh);
    cudaGetSymbolAddress((void**)&vh,  g_vh);
    cudaGetSymbolAddress((void**)&ctx16, g_ctx16);
    cudaGetSymbolAddress((void**)&x116,  g_x116);
    cudaGetSymbolAddress((void**)&h116,  g_h116);
    cudaGetSymbolAddress((void**)&wkT16, g_wkT16);
    cudaGetSymbolAddress((void**)&wvT16, g_wvT16);
    cudaGetSymbolAddress((void**)&woT16, g_woT16);
    cudaGetSymbolAddress((void**)&w1T16, g_w1T16);
    cudaGetSymbolAddress((void**)&w2T16, g_w2T16);

    cudaFuncSetAttribute(attn_mma, cudaFuncAttributeMaxDynamicSharedMemorySize, ATTN_SMEM);
    cudaFuncSetAttribute(gemm_h<false,false>, cudaFuncAttributeMaxDynamicSharedMemorySize, GEMM_H_SMEM);
    cudaFuncSetAttribute(gemm_h<true, true >, cudaFuncAttributeMaxDynamicSharedMemorySize, GEMM_H_SMEM);
    cudaFuncSetAttribute(gemm_proj3_h, cudaFuncAttributeMaxDynamicSharedMemorySize, GEMM_H_SMEM);

    // ---- prep ----
    conv_fp16_3<<<dim3(512, 1, 3), 256>>>(query, key, values, in16q, in16k, in16v);
    transpose_h_all<<<dim3(64, 64, 5), 256>>>(Wk, Wv, Wo, W1, W2,
                                              wkT16, wvT16, woT16, w1T16, w2T16);

    const dim3 gProj (DD / 128,   MROWS / 128);
    const dim3 gProj3(DD / 128,   MROWS / 128, 3);
    const dim3 gFF1  (DFFN / 128, MROWS / 128);

    gemm_proj3_h<<<gProj3, 256, GEMM_H_SMEM>>>(in16q, in16k, in16v, wkT16, wvT16,
                                               bk, bv, qh, kh, vh);

    attn_mma<<<dim3(SS / TQ, HH, BB), 256, ATTN_SMEM>>>(qh, kh, vh, gammas, ctx16);

    gemm_h<false,false><<<gProj, 256, GEMM_H_SMEM>>>(ctx16, woT16, bo, ao, (__half*)0,
                                                     MROWS, DD, DD);

    add_ln<<<MROWS, 256>>>(query, ao, ln1_g, ln1_b, x1, x116);

    gemm_h<true, true ><<<gFF1, 256, GEMM_H_SMEM>>>(x116, w1T16, b1, (float*)0, h116,
                                                    MROWS, DFFN, DD);
    gemm_h<false,false><<<gProj, 256, GEMM_H_SMEM>>>(h116, w2T16, b2, f2, (__half*)0,
                                                     MROWS, DD, DFFN);

    add_ln<<<MROWS, 256>>>(x1, f2, ln2_g, ln2_b, out, (__half*)0);
}

// round 9
// speedup vs baseline: 5.9078x; 1.0393x over previous
#include <cuda_runtime.h>
#include <cuda_fp16.h>
#include <cstdint>
#include <math.h>

// Problem constants
#define BB   16
#define SS   512
#define DD   512
#define HH   8
#define DK   64
#define DFFN 2048
#define MROWS (BB*SS)   // 8192

// ---------------- scratch (static device globals; no allocation) ----------------
__device__ float g_ao [MROWS*DD];
__device__ float g_x1 [MROWS*DD];
__device__ float g_f2 [MROWS*DD];
__device__ __half g_in16q[MROWS*DD];
__device__ __half g_in16k[MROWS*DD];
__device__ __half g_in16v[MROWS*DD];
__device__ __half g_qh  [MROWS*DD];
__device__ __half g_kh  [MROWS*DD];
__device__ __half g_vh  [MROWS*DD];
__device__ __half g_ctx16[MROWS*DD];
__device__ __half g_x116 [MROWS*DD];
__device__ __half g_h116 [MROWS*DFFN];
__device__ __half g_wkT16[DD*DD];
__device__ __half g_wvT16[DD*DD];
__device__ __half g_woT16[DD*DD];
__device__ __half g_w1T16[DFFN*DD];
__device__ __half g_w2T16[DD*DFFN];

// ---------------- helpers ----------------
__device__ __forceinline__ uint32_t smem_to_u32(const void* p) {
    uint32_t a;
    asm("{ .reg .u64 tmp; cvta.to.shared.u64 tmp, %1; cvt.u32.u64 %0, tmp; }" : "=r"(a) : "l"(p));
    return a;
}
#define CP_ASYNC16(saddr, gptr) \
    asm volatile("cp.async.cg.shared.global [%0], [%1], 16;" :: "r"(saddr), "l"(gptr))
#define CP_COMMIT() asm volatile("cp.async.commit_group;" ::: "memory")
#define CP_WAIT0()  asm volatile("cp.async.wait_group 0;" ::: "memory")
#define CP_WAIT1()  asm volatile("cp.async.wait_group 1;" ::: "memory")

__device__ __forceinline__ void mma_f16(float* c, const uint32_t* a, const uint32_t* b) {
    asm volatile(
        "mma.sync.aligned.m16n8k16.row.col.f32.f16.f16.f32 "
        "{%0,%1,%2,%3}, {%4,%5,%6,%7}, {%8,%9}, {%0,%1,%2,%3};"
        : "+f"(c[0]), "+f"(c[1]), "+f"(c[2]), "+f"(c[3])
        : "r"(a[0]), "r"(a[1]), "r"(a[2]), "r"(a[3]), "r"(b[0]), "r"(b[1]));
}
__device__ __forceinline__ void ldmx4(uint32_t* r, uint32_t addr) {
    asm volatile("ldmatrix.sync.aligned.m8n8.x4.shared.b16 {%0,%1,%2,%3}, [%4];"
                 : "=r"(r[0]), "=r"(r[1]), "=r"(r[2]), "=r"(r[3]) : "r"(addr));
}
__device__ __forceinline__ void ldmx2(uint32_t& r0, uint32_t& r1, uint32_t addr) {
    asm volatile("ldmatrix.sync.aligned.m8n8.x2.shared.b16 {%0,%1}, [%2];"
                 : "=r"(r0), "=r"(r1) : "r"(addr));
}
__device__ __forceinline__ void ldmx2_trans(uint32_t& r0, uint32_t& r1, uint32_t addr) {
    asm volatile("ldmatrix.sync.aligned.m8n8.x2.trans.shared.b16 {%0,%1}, [%2];"
                 : "=r"(r0), "=r"(r1) : "r"(addr));
}

__device__ __forceinline__ float fexp(float x) {
    float y;
    asm("ex2.approx.f32 %0, %1;" : "=f"(y) : "f"(x * 1.4426950408889634f));
    return y;
}
__device__ __forceinline__ float fsqrt_ap(float x) {
    float y;
    asm("sqrt.approx.f32 %0, %1;" : "=f"(y) : "f"(x));
    return y;
}

// ========================= fp16 mma GEMM (ldmatrix fragments) =========================
#define HP 72
#define TILE_H (128*HP)
#define STAGE_H (2*TILE_H)
#define GEMM_H_SMEM (2*STAGE_H*(int)sizeof(__half))

__device__ __forceinline__ void fill_h(const __half* __restrict__ A,
                                       const __half* __restrict__ Bt,
                                       int K, int bm, int bn, int kc,
                                       uint32_t sA, uint32_t sB, int t)
{
#pragma unroll
    for (int i = 0; i < 4; i++) {
        int id = t + i * 256;
        int row = id >> 3, c = id & 7;
        CP_ASYNC16(sA + (uint32_t)(row * HP + c * 8) * 2u,
                   A + (size_t)(bm + row) * K + kc * 64 + c * 8);
    }
#pragma unroll
    for (int i = 0; i < 4; i++) {
        int id = t + i * 256;
        int row = id >> 3, c = id & 7;
        CP_ASYNC16(sB + (uint32_t)(row * HP + c * 8) * 2u,
                   Bt + (size_t)(bn + row) * K + kc * 64 + c * 8);
    }
}

template<bool RELU, bool OUT16>
__device__ __forceinline__ void gemm_h_body(const __half* __restrict__ A,
                                            const __half* __restrict__ Bt,
                                            const float* __restrict__ bias,
                                            float* __restrict__ C,
                                            __half* __restrict__ C16,
                                            int N, int K, int bm, int bn,
                                            __half* smem_h)
{
    const int t    = threadIdx.x;
    const int lane = t & 31, wid = t >> 5;
    const int g    = lane >> 2, tg = lane & 3;
    const int wm   = (wid >> 2) * 64;
    const int wn   = (wid & 3) * 32;
    const int r8   = lane & 7, quad = lane >> 3;
    // ldmatrix lane offsets
    const int rowA = (quad & 1) * 8 + r8, colA = (quad >> 1) * 8;   // A x4
    const int rowB = (quad >> 1) * 8 + r8, colB = (quad & 1) * 8;   // B x4 (pairs)
    const uint32_t sbase = smem_to_u32(smem_h);

    float acc[4][4][4];
#pragma unroll
    for (int mt = 0; mt < 4; mt++)
#pragma unroll
        for (int nt = 0; nt < 4; nt++)
#pragma unroll
            for (int r = 0; r < 4; r++) acc[mt][nt][r] = 0.f;

    const int nk = K >> 6;

    fill_h(A, Bt, K, bm, bn, 0, sbase, sbase + TILE_H * 2, t);
    CP_COMMIT();

    for (int kc = 0; kc < nk; kc++) {
        CP_WAIT0();
        __syncthreads();
        if (kc + 1 < nk) {
            const uint32_t off = ((kc + 1) & 1) * (uint32_t)(STAGE_H * 2);
            fill_h(A, Bt, K, bm, bn, kc + 1, sbase + off, sbase + off + TILE_H * 2, t);
            CP_COMMIT();
        }
        const uint32_t aSa = sbase + (uint32_t)((kc & 1) * STAGE_H) * 2u;
        const uint32_t bSa = aSa + (uint32_t)TILE_H * 2u;

#pragma unroll
        for (int ks = 0; ks < 4; ks++) {
            const int k0 = ks * 16;
            uint32_t af[4][4];
#pragma unroll
            for (int mt = 0; mt < 4; mt++)
                ldmx4(af[mt], aSa + (uint32_t)((wm + mt * 16 + rowA) * HP + k0 + colA) * 2u);
            uint32_t bf[4][2];
#pragma unroll
            for (int nh = 0; nh < 2; nh++) {
                uint32_t b4[4];
                ldmx4(b4, bSa + (uint32_t)((wn + nh * 16 + rowB) * HP + k0 + colB) * 2u);
                bf[2*nh  ][0] = b4[0]; bf[2*nh  ][1] = b4[1];
                bf[2*nh+1][0] = b4[2]; bf[2*nh+1][1] = b4[3];
            }
#pragma unroll
            for (int mt = 0; mt < 4; mt++)
#pragma unroll
                for (int nt = 0; nt < 4; nt++)
                    mma_f16(acc[mt][nt], af[mt], bf[nt]);
        }
    }

#pragma unroll
    for (int mt = 0; mt < 4; mt++) {
#pragma unroll
        for (int nt = 0; nt < 4; nt++) {
            const int row0 = bm + wm + mt * 16 + g;
            const int col  = bn + wn + nt * 8 + 2 * tg;
            float b0 = bias[col], b1 = bias[col + 1];
            float v0 = acc[mt][nt][0] + b0, v1 = acc[mt][nt][1] + b1;
            float v2 = acc[mt][nt][2] + b0, v3 = acc[mt][nt][3] + b1;
            if (RELU) {
                v0 = fmaxf(v0, 0.f); v1 = fmaxf(v1, 0.f);
                v2 = fmaxf(v2, 0.f); v3 = fmaxf(v3, 0.f);
            }
            if (OUT16) {
                *(__half2*)(C16 + (size_t)row0 * N + col)       = __floats2half2_rn(v0, v1);
                *(__half2*)(C16 + (size_t)(row0 + 8) * N + col) = __floats2half2_rn(v2, v3);
            } else {
                *(float2*)(C + (size_t)row0 * N + col)       = make_float2(v0, v1);
                *(float2*)(C + (size_t)(row0 + 8) * N + col) = make_float2(v2, v3);
            }
        }
    }
}

template<bool RELU, bool OUT16>
__global__ __launch_bounds__(256, 2)
void gemm_h(const __half* __restrict__ A, const __half* __restrict__ Bt,
            const float* __restrict__ bias, float* __restrict__ C,
            __half* __restrict__ C16, int M, int N, int K)
{
    extern __shared__ __align__(16) __half smem_h[];
    gemm_h_body<RELU, OUT16>(A, Bt, bias, C, C16, N, K,
                             blockIdx.y * 128, blockIdx.x * 128, smem_h);
}

__global__ __launch_bounds__(256, 2)
void gemm_proj3_h(const __half* __restrict__ A0, const __half* __restrict__ A1,
                  const __half* __restrict__ A2,
                  const __half* __restrict__ WkT, const __half* __restrict__ WvT,
                  const float* __restrict__ bk, const float* __restrict__ bv,
                  __half* __restrict__ C0, __half* __restrict__ C1, __half* __restrict__ C2)
{
    extern __shared__ __align__(16) __half smem_h[];
    const int z = blockIdx.z;
    const __half* A = (z == 0) ? A0 : (z == 1) ? A1 : A2;
    const __half* W = (z == 2) ? WvT : WkT;
    const float* bias = (z == 2) ? bv : bk;
    __half* C16 = (z == 0) ? C0 : (z == 1) ? C1 : C2;
    gemm_h_body<false, true>(A, W, bias, ((float*)0), C16, DD, DD,
                             blockIdx.y * 128, blockIdx.x * 128, smem_h);
}

// ---------------- prep kernels ----------------
__global__ __launch_bounds__(256)
void conv_fp16_3(const float* __restrict__ s0, const float* __restrict__ s1,
                 const float* __restrict__ s2,
                 __half* __restrict__ d0, __half* __restrict__ d1, __half* __restrict__ d2)
{
    const int z = blockIdx.z;
    const float* s = (z == 0) ? s0 : (z == 1) ? s1 : s2;
    __half* d = (z == 0) ? d0 : (z == 1) ? d1 : d2;
    const int n4 = MROWS * DD / 4;
    for (int i = blockIdx.x * 256 + threadIdx.x; i < n4; i += gridDim.x * 256) {
        float4 v = ((const float4*)s)[i];
        ((__half2*)d)[2 * i    ] = __floats2half2_rn(v.x, v.y);
        ((__half2*)d)[2 * i + 1] = __floats2half2_rn(v.z, v.w);
    }
}

__global__ __launch_bounds__(256)
void transpose_h_all(const float* __restrict__ Wk, const float* __restrict__ Wv,
                     const float* __restrict__ Wo, const float* __restrict__ W1,
                     const float* __restrict__ W2,
                     __half* __restrict__ o0, __half* __restrict__ o1,
                     __half* __restrict__ o2, __half* __restrict__ o3,
                     __half* __restrict__ o4)
{
    const int z = blockIdx.z;
    const float* in; __half* out; int R, C;
    switch (z) {
        case 0: in = Wk; out = o0; R = DD;   C = DD;   break;
        case 1: in = Wv; out = o1; R = DD;   C = DD;   break;
        case 2: in = Wo; out = o2; R = DD;   C = DD;   break;
        case 3: in = W1; out = o3; R = DD;   C = DFFN; break;
        default:in = W2; out = o4; R = DFFN; C = DD;   break;
    }
    const int bx = blockIdx.x * 32;
    const int by = blockIdx.y * 32;
    if (bx >= C || by >= R) return;
    __shared__ float tile[32][33];
    const int tx = threadIdx.x & 31;
    const int ty = threadIdx.x >> 5;
#pragma unroll
    for (int i = 0; i < 32; i += 8)
        tile[ty + i][tx] = in[(size_t)(by + ty + i) * C + bx + tx];
    __syncthreads();
#pragma unroll
    for (int i = 0; i < 32; i += 8)
        out[(size_t)(bx + ty + i) * R + by + tx] = __float2half(tile[tx][ty + i]);
}

// ========================= Fused AKT attention (fp16 mma, 512 thr) =========================
#define TQ   16
#define CH   128
#define RP   516            // fp32 score pitch (floats)
#define PP   520            // fp16 prob pitch (halves)
#define QP   72
#define KVP  72
#define KVBUF (128*KVP)
#define OFF_P   33024
#define OFF_Q   (33024+16640)
#define OFF_KV  (33024+16640+2304)
#define ATTN_SMEM (33024+16640+2304+36864)

__global__ __launch_bounds__(512, 2)
void attn_mma(const __half* __restrict__ Q, const __half* __restrict__ K,
              const __half* __restrict__ V, const float* __restrict__ gammas,
              __half* __restrict__ CTX16)
{
    extern __shared__ __align__(16) char smem_c[];
    float*  sRaw = (float*)smem_c;
    __half* sP   = (__half*)(smem_c + OFF_P);
    __half* sQ   = (__half*)(smem_c + OFF_Q);
    __half* sKV  = (__half*)(smem_c + OFF_KV);
    const uint32_t sQa  = smem_to_u32(sQ);
    const uint32_t sPa  = smem_to_u32(sP);
    const uint32_t sKVa = smem_to_u32(sKV);

    const int t    = threadIdx.x;
    const int lane = t & 31, w = t >> 5;              // 16 warps
    const int g    = lane >> 2, tg = lane & 3;
    const int r8   = lane & 7, quad = lane >> 3;
    const int rowA = (quad & 1) * 8 + r8, colA = (quad >> 1) * 8;  // A x4 offsets
    const int qt = blockIdx.x, h = blockIdx.y, b = blockIdx.z;
    const int i0 = qt * TQ;
    const int nch = (i0 + TQ + CH - 1) >> 7;

    // Q tile 16x64 fp16 (group 0)
    if (t < 128) {
        int r = t >> 3, c8 = t & 7;
        CP_ASYNC16(sQa + (uint32_t)(r * QP + c8 * 8) * 2u,
                   Q + (size_t)(b * SS + i0 + r) * DD + h * 64 + c8 * 8);
    }
    CP_COMMIT();
    // K chunk 0 (group 1)
    {
        const __half* Kb = K + (size_t)(b * SS) * DD + h * 64;
#pragma unroll
        for (int i = 0; i < 2; i++) {
            int id = t + i * 512;
            int r = id >> 3, c8 = id & 7;
            CP_ASYNC16(sKVa + (uint32_t)(r * KVP + c8 * 8) * 2u,
                       Kb + (size_t)r * DD + c8 * 8);
        }
    }
    CP_COMMIT();

    // tail init of sRaw
    {
        const int j0i = nch * CH;
        const int nf4 = (512 - j0i) >> 2;
        if (nf4 > 0) {
            for (int idx = t; idx < 16 * nf4; idx += 512) {
                int r = idx / nf4, c = idx - r * nf4;
                *(float4*)(sRaw + r * RP + j0i + c * 4) =
                    make_float4(-1e32f, -1e32f, -1e32f, -1e32f);
            }
        }
    }

    // hoist Q fragments via ldmatrix.x4
    CP_WAIT1();
    __syncthreads();
    uint32_t qf[4][4];
#pragma unroll
    for (int ks = 0; ks < 4; ks++)
        ldmx4(qf[ks], sQa + (uint32_t)(rowA * QP + ks * 16 + colA) * 2u);

    // -------- Phase A: warp w owns j-cols [w*8, w*8+8) of each 128-chunk --------
    const int q2 = (lane >> 3) & 1;   // ldmatrix.x2 lane offsets (lanes 0-15 matter)
    for (int c = 0; c < nch; c++) {
        CP_WAIT0();
        __syncthreads();
        if (c + 1 < nch) {
            const __half* Kb = K + (size_t)(b * SS + (c + 1) * CH) * DD + h * 64;
            const uint32_t dst = sKVa + (uint32_t)(((c + 1) & 1) * KVBUF) * 2u;
#pragma unroll
            for (int i = 0; i < 2; i++) {
                int id = t + i * 512;
                int r = id >> 3, c8 = id & 7;
                CP_ASYNC16(dst + (uint32_t)(r * KVP + c8 * 8) * 2u,
                           Kb + (size_t)r * DD + c8 * 8);
            }
            CP_COMMIT();
        }
        const uint32_t kba = sKVa + (uint32_t)((c & 1) * KVBUF) * 2u;

        float acc[4] = {0.f, 0.f, 0.f, 0.f};
#pragma unroll
        for (int ks = 0; ks < 4; ks++) {
            uint32_t bf[2];
            ldmx2(bf[0], bf[1],
                  kba + (uint32_t)((w * 8 + r8) * KVP + ks * 16 + q2 * 8) * 2u);
            mma_f16(acc, qf[ks], bf);
        }
        const int ilo = i0 + g, ihi = i0 + g + 8;
        const int j = c * CH + w * 8 + 2 * tg;
        sRaw[(g    ) * RP + j    ] = (j     <= ilo) ? acc[0] : -1e32f;
        sRaw[(g    ) * RP + j + 1] = (j + 1 <= ilo) ? acc[1] : -1e32f;
        sRaw[(g + 8) * RP + j    ] = (j     <= ihi) ? acc[2] : -1e32f;
        sRaw[(g + 8) * RP + j + 1] = (j + 1 <= ihi) ? acc[3] : -1e32f;
    }
    __syncthreads();

    // prefetch V chunk 0 (overlaps Phase B)
    {
        const __half* Vb = V + (size_t)(b * SS) * DD + h * 64;
#pragma unroll
        for (int i = 0; i < 2; i++) {
            int id = t + i * 512;
            int r = id >> 3, c8 = id & 7;
            CP_ASYNC16(sKVa + (uint32_t)(r * KVP + c8 * 8) * 2u,
                       Vb + (size_t)r * DD + c8 * 8);
        }
    }
    CP_COMMIT();

    // -------- Phase B: one row per warp --------
    {
        float gm  = gammas[h];
        float sp  = (gm > 20.f) ? gm : log1pf(expf(gm));
        float gamma = -sp;
        const int row_i = w;
        const int ig = i0 + row_i;
        const float4* rv = (const float4*)(sRaw + row_i * RP);

        float vals[16];
#pragma unroll
        for (int u = 0; u < 4; u++) {
            float4 v4 = rv[lane * 4 + u];
            vals[4*u+0] = 0.125f * v4.x; vals[4*u+1] = 0.125f * v4.y;
            vals[4*u+2] = 0.125f * v4.z; vals[4*u+3] = 0.125f * v4.w;
        }

        float mx = -1e32f;
#pragma unroll
        for (int m = 0; m < 16; m++) mx = fmaxf(mx, vals[m]);
#pragma unroll
        for (int off = 16; off > 0; off >>= 1) mx = fmaxf(mx, __shfl_xor_sync(0xffffffffu, mx, off));

        float p[16]; float s = 0.f;
#pragma unroll
        for (int m = 0; m < 16; m++) { p[m] = fexp(vals[m] - mx); s += p[m]; }
#pragma unroll
        for (int off = 16; off > 0; off >>= 1) s += __shfl_xor_sync(0xffffffffu, s, off);
        const float inv = 1.f / s;

        float local = 0.f; float cum[16];
#pragma unroll
        for (int m = 0; m < 16; m++) { local += p[m] * inv; cum[m] = local; }
        float run = local;
#pragma unroll
        for (int off = 1; off < 32; off <<= 1) {
            float vv = __shfl_up_sync(0xffffffffu, run, off);
            if (lane >= off) run += vv;
        }
        const float prefix = run - local;
        const float total  = __shfl_sync(0xffffffffu, run, 31);

#pragma unroll
        for (int m = 0; m < 16; m++) {
            int jg = lane * 16 + m;
            float suffix = fmaxf(total - (prefix + cum[m]), 0.f);
            float pe = fabsf((float)(ig - jg));
            float dist = fsqrt_ap(suffix * pe);
            float eff = fexp(dist * gamma);
            eff = fminf(fmaxf(eff, 1e-5f), 1e5f);
            vals[m] = vals[m] * eff;
        }

        float mx2 = -1e32f;
#pragma unroll
        for (int m = 0; m < 16; m++) mx2 = fmaxf(mx2, vals[m]);
#pragma unroll
        for (int off = 16; off > 0; off >>= 1) mx2 = fmaxf(mx2, __shfl_xor_sync(0xffffffffu, mx2, off));
        float s2 = 0.f;
#pragma unroll
        for (int m = 0; m < 16; m++) { vals[m] = fexp(vals[m] - mx2); s2 += vals[m]; }
#pragma unroll
        for (int off = 16; off > 0; off >>= 1) s2 += __shfl_xor_sync(0xffffffffu, s2, off);
        const float inv2 = 1.f / s2;

        __half2* wp = (__half2*)(sP + row_i * PP + lane * 16);
#pragma unroll
        for (int u = 0; u < 8; u++)
            wp[u] = __floats2half2_rn(vals[2*u] * inv2, vals[2*u+1] * inv2);
    }
    __syncthreads();

    // -------- Phase C: warp pair (w, w+8): d-cols (w&7)*8, k-half (w>>3) --------
    float oc[4] = {0.f, 0.f, 0.f, 0.f};
    const int kslice = (w >> 3) * 64;
    const int dcol   = (w & 7) * 8;
    const int lrow   = lane & 15;
    for (int c = 0; c < nch; c++) {
        CP_WAIT0();
        __syncthreads();
        if (c + 1 < nch) {
            const __half* Vb = V + (size_t)(b * SS + (c + 1) * CH) * DD + h * 64;
            const uint32_t dst = sKVa + (uint32_t)(((c + 1) & 1) * KVBUF) * 2u;
#pragma unroll
            for (int i = 0; i < 2; i++) {
                int id = t + i * 512;
                int r = id >> 3, c8 = id & 7;
                CP_ASYNC16(dst + (uint32_t)(r * KVP + c8 * 8) * 2u,
                           Vb + (size_t)r * DD + c8 * 8);
            }
            CP_COMMIT();
        }
        const uint32_t vba = sKVa + (uint32_t)((c & 1) * KVBUF) * 2u;

#pragma unroll
        for (int kk = 0; kk < 64; kk += 16) {
            const int k0 = kslice + kk;
            const int jcol = c * CH + k0;
            uint32_t af[4];
            ldmx4(af, sPa + (uint32_t)(rowA * PP + jcol + colA) * 2u);
            uint32_t bf[2];
            ldmx2_trans(bf[0], bf[1],
                        vba + (uint32_t)((k0 + lrow) * KVP + dcol) * 2u);
            mma_f16(oc, af, bf);
        }
    }
    __syncthreads();
    // reduce k-halves: warps 8-15 stage partials, warps 0-7 combine + write
    if (w >= 8)
        ((float4*)sRaw)[(w - 8) * 32 + lane] = make_float4(oc[0], oc[1], oc[2], oc[3]);
    __syncthreads();
    if (w < 8) {
        float4 o2 = ((float4*)sRaw)[w * 32 + lane];
        oc[0] += o2.x; oc[1] += o2.y; oc[2] += o2.z; oc[3] += o2.w;
        const int col = h * 64 + dcol + 2 * tg;
        *(__half2*)(CTX16 + (size_t)(b * SS + i0 + g    ) * DD + col) = __floats2half2_rn(oc[0], oc[1]);
        *(__half2*)(CTX16 + (size_t)(b * SS + i0 + g + 8) * DD + col) = __floats2half2_rn(oc[2], oc[3]);
    }
}

// ---------------- residual add + LayerNorm (optional fp16 side copy) ----------------
__global__ __launch_bounds__(256)
void add_ln(const float* __restrict__ A, const float* __restrict__ B,
            const float* __restrict__ g, const float* __restrict__ be,
            float* __restrict__ O, __half* __restrict__ O16)
{
    const int row = blockIdx.x;
    const int t = threadIdx.x;
    const float* a = A + (size_t)row * DD;
    const float* b = B + (size_t)row * DD;

    float x0 = a[t] + b[t];
    float x1 = a[t + 256] + b[t + 256];
    float s  = x0 + x1;
    float sq = x0 * x0 + x1 * x1;

    __shared__ float rs[8], rq[8];
    __shared__ float sMu, sRstd;
    const int lane = t & 31, w = t >> 5;
#pragma unroll
    for (int off = 16; off > 0; off >>= 1) {
        s  += __shfl_xor_sync(0xffffffffu, s, off);
        sq += __shfl_xor_sync(0xffffffffu, sq, off);
    }
    if (lane == 0) { rs[w] = s; rq[w] = sq; }
    __syncthreads();
    if (t == 0) {
        float S = 0.f, SQ = 0.f;
#pragma unroll
        for (int i = 0; i < 8; i++) { S += rs[i]; SQ += rq[i]; }
        float mu = S * (1.f / 512.f);
        float var = fmaxf(SQ * (1.f / 512.f) - mu * mu, 0.f);
        sMu = mu;
        sRstd = rsqrtf(var + 1e-5f);
    }
    __syncthreads();
    const float mu = sMu, rstd = sRstd;
    float y0 = (x0 - mu) * rstd * g[t]       + be[t];
    float y1 = (x1 - mu) * rstd * g[t + 256] + be[t + 256];
    O[(size_t)row * DD + t]       = y0;
    O[(size_t)row * DD + t + 256] = y1;
    if (O16) {
        O16[(size_t)row * DD + t]       = __float2half(y0);
        O16[(size_t)row * DD + t + 256] = __float2half(y1);
    }
}

// ---------------- launch ----------------
extern "C" void kernel_launch(void* const* d_in, const int* in_sizes, int n_in,
                              void* d_out, int out_size)
{
    const float* query  = (const float*)d_in[0];
    const float* key    = (const float*)d_in[1];
    const float* values = (const float*)d_in[2];
    const float* Wk     = (const float*)d_in[3];
    const float* bk     = (const float*)d_in[4];
    const float* Wv     = (const float*)d_in[5];
    const float* bv     = (const float*)d_in[6];
    const float* Wo     = (const float*)d_in[7];
    const float* bo     = (const float*)d_in[8];
    const float* gammas = (const float*)d_in[9];
    const float* ln1_g  = (const float*)d_in[10];
    const float* ln1_b  = (const float*)d_in[11];
    const float* W1     = (const float*)d_in[12];
    const float* b1     = (const float*)d_in[13];
    const float* W2     = (const float*)d_in[14];
    const float* b2     = (const float*)d_in[15];
    const float* ln2_g  = (const float*)d_in[16];
    const float* ln2_b  = (const float*)d_in[17];
    float* out = (float*)d_out;

    float *ao, *x1, *f2;
    __half *in16q, *in16k, *in16v, *qh, *kh, *vh, *ctx16, *x116, *h116;
    __half *wkT16, *wvT16, *woT16, *w1T16, *w2T16;
    cudaGetSymbolAddress((void**)&ao,  g_ao);
    cudaGetSymbolAddress((void**)&x1,  g_x1);
    cudaGetSymbolAddress((void**)&f2,  g_f2);
    cudaGetSymbolAddress((void**)&in16q, g_in16q);
    cudaGetSymbolAddress((void**)&in16k, g_in16k);
    cudaGetSymbolAddress((void**)&in16v, g_in16v);
    cudaGetSymbolAddress((void**)&qh,  g_qh);
    cudaGetSymbolAddress((void**)&kh,  g_kh);
    cudaGetSymbolAddress((void**)&vh,  g_vh);
    cudaGetSymbolAddress((void**)&ctx16, g_ctx16);
    cudaGetSymbolAddress((void**)&x116,  g_x116);
    cudaGetSymbolAddress((void**)&h116,  g_h116);
    cudaGetSymbolAddress((void**)&wkT16, g_wkT16);
    cudaGetSymbolAddress((void**)&wvT16, g_wvT16);
    cudaGetSymbolAddress((void**)&woT16, g_woT16);
    cudaGetSymbolAddress((void**)&w1T16, g_w1T16);
    cudaGetSymbolAddress((void**)&w2T16, g_w2T16);

    cudaFuncSetAttribute(attn_mma, cudaFuncAttributeMaxDynamicSharedMemorySize, ATTN_SMEM);
    cudaFuncSetAttribute(gemm_h<false,false>, cudaFuncAttributeMaxDynamicSharedMemorySize, GEMM_H_SMEM);
    cudaFuncSetAttribute(gemm_h<true, true >, cudaFuncAttributeMaxDynamicSharedMemorySize, GEMM_H_SMEM);
    cudaFuncSetAttribute(gemm_proj3_h, cudaFuncAttributeMaxDynamicSharedMemorySize, GEMM_H_SMEM);

    // ---- prep ----
    conv_fp16_3<<<dim3(512, 1, 3), 256>>>(query, key, values, in16q, in16k, in16v);
    transpose_h_all<<<dim3(64, 64, 5), 256>>>(Wk, Wv, Wo, W1, W2,
                                              wkT16, wvT16, woT16, w1T16, w2T16);

    const dim3 gProj (DD / 128,   MROWS / 128);
    const dim3 gProj3(DD / 128,   MROWS / 128, 3);
    const dim3 gFF1  (DFFN / 128, MROWS / 128);

    gemm_proj3_h<<<gProj3, 256, GEMM_H_SMEM>>>(in16q, in16k, in16v, wkT16, wvT16,
                                               bk, bv, qh, kh, vh);

    attn_mma<<<dim3(SS / TQ, HH, BB), 512, ATTN_SMEM>>>(qh, kh, vh, gammas, ctx16);

    gemm_h<false,false><<<gProj, 256, GEMM_H_SMEM>>>(ctx16, woT16, bo, ao, (__half*)0,
                                                     MROWS, DD, DD);

    add_ln<<<MROWS, 256>>>(query, ao, ln1_g, ln1_b, x1, x116);

    gemm_h<true, true ><<<gFF1, 256, GEMM_H_SMEM>>>(x116, w1T16, b1, (float*)0, h116,
                                                    MROWS, DFFN, DD);
    gemm_h<false,false><<<gProj, 256, GEMM_H_SMEM>>>(h116, w2T16, b2, f2, (__half*)0,
                                                     MROWS, DD, DFFN);

    add_ln<<<MROWS, 256>>>(x1, f2, ln2_g, ln2_b, out, (__half*)0);
}